// round 4
// baseline (speedup 1.0000x reference)
#include <cuda_runtime.h>
#include <math.h>

#define D 256
#define T_ 1024
#define NN 64
#define ROWS 65536   // T_*NN
#define M 64

// output layout (concatenated, fp32)
#define OFF_UQ 0UL                  // (512,1024,64) = 33554432
#define OFF_UM 33554432UL           // (64,256)      = 16384
#define OFF_SQ 33570816UL           // (65536,64)    = 4194304
#define OFF_SM 37765120UL           // (65536,64)    = 4194304
#define OFF_SP 41959424UL           // (65536,)      = 65536
#define OFF_GL 42024960UL           // (65536,256)   = 16777216

typedef unsigned long long ull;

// ---------------- scratch (static device globals; no allocations) ------------
__device__ float    g_score[ROWS * M];    // raw scores, 16 MB
__device__ float    g_keysT[D * M];       // keys transposed [d][m]
__device__ unsigned g_cmax_u[M];          // ordered-encoded column max
__device__ float    g_csum[M];            // column sum of exp(s-cmax)
__device__ int      g_top1[ROWS];
__device__ int      g_top2i[ROWS];
__device__ float    g_qupd[M * D];

// ---------------- helpers ----------------------------------------------------
__device__ __forceinline__ ull pack2(float lo, float hi) {
    ull r; asm("mov.b64 %0, {%1, %2};" : "=l"(r) : "f"(lo), "f"(hi)); return r;
}
__device__ __forceinline__ void unpack2(ull v, float& lo, float& hi) {
    asm("mov.b64 {%0, %1}, %2;" : "=f"(lo), "=f"(hi) : "l"(v));
}
__device__ __forceinline__ ull fma2(ull a, ull b, ull c) {
    ull d; asm("fma.rn.f32x2 %0, %1, %2, %3;" : "=l"(d) : "l"(a), "l"(b), "l"(c));
    return d;
}
__device__ __forceinline__ unsigned enc_f(float f) {
    unsigned u = __float_as_uint(f);
    return (u & 0x80000000u) ? ~u : (u | 0x80000000u);
}
__device__ __forceinline__ float dec_f(unsigned e) {
    return (e & 0x80000000u) ? __uint_as_float(e & 0x7fffffffu) : __uint_as_float(~e);
}

// ---------------- K0: init + keys transpose -----------------------------------
__global__ void k0_init(const float* __restrict__ keys) {
    int i = blockIdx.x * 256 + threadIdx.x;   // 64*256 = 16384 threads
    int m = i >> 8, d = i & 255;
    g_keysT[d * M + m] = keys[i];
    g_qupd[i] = 0.0f;
    if (i < M) { g_cmax_u[i] = 0u; g_csum[i] = 0.0f; }
}

// ---------------- K1: score GEMM + row softmax + top2 + colmax partials -------
__global__ __launch_bounds__(256) void k1_score(const float* __restrict__ q,
                                                float* __restrict__ out_sm) {
    const int tid = threadIdx.x;
    const int row = blockIdx.x * 256 + tid;
    const int lane = tid & 31, wid = tid >> 5;

    ull acc[32];
#pragma unroll
    for (int j = 0; j < 32; ++j) acc[j] = 0ull;

    const ulonglong2* ks2 = (const ulonglong2*)g_keysT;  // [d][m/4] pairs-of-pairs

#pragma unroll 4
    for (int d = 0; d < D; ++d) {
        float qv = __ldg(&q[d * ROWS + row]);
        ull q2 = pack2(qv, qv);
#pragma unroll
        for (int jj = 0; jj < 16; ++jj) {
            ulonglong2 kk = __ldg(&ks2[d * 16 + jj]);
            acc[2 * jj]     = fma2(q2, kk.x, acc[2 * jj]);
            acc[2 * jj + 1] = fma2(q2, kk.y, acc[2 * jj + 1]);
        }
    }

    float s[64];
#pragma unroll
    for (int j = 0; j < 32; ++j) unpack2(acc[j], s[2 * j], s[2 * j + 1]);

    // raw scores to scratch
#pragma unroll
    for (int j = 0; j < 16; ++j) {
        float4 t = make_float4(s[4 * j], s[4 * j + 1], s[4 * j + 2], s[4 * j + 3]);
        ((float4*)(g_score + (size_t)row * 64))[j] = t;
    }

    // top-2 (strict > keeps lowest index on ties, matching lax.top_k)
    float v1 = -1e30f, v2 = -1e30f; int i1 = 0, i2 = 0;
#pragma unroll
    for (int m = 0; m < 64; ++m) {
        float v = s[m];
        if (v > v1) { v2 = v1; i2 = i1; v1 = v; i1 = m; }
        else if (v > v2) { v2 = v; i2 = m; }
    }

    // column-max block partials
    __shared__ float wpart[8 * 64];
#pragma unroll
    for (int m = 0; m < 64; ++m) {
        float v = s[m];
        v = fmaxf(v, __shfl_xor_sync(0xffffffffu, v, 16));
        v = fmaxf(v, __shfl_xor_sync(0xffffffffu, v, 8));
        v = fmaxf(v, __shfl_xor_sync(0xffffffffu, v, 4));
        v = fmaxf(v, __shfl_xor_sync(0xffffffffu, v, 2));
        v = fmaxf(v, __shfl_xor_sync(0xffffffffu, v, 1));
        if (lane == 0) wpart[wid * 64 + m] = v;
    }
    __syncthreads();
    if (tid < 64) {
        float mx = wpart[tid];
#pragma unroll
        for (int w = 1; w < 8; ++w) mx = fmaxf(mx, wpart[w * 64 + tid]);
        atomicMax(&g_cmax_u[tid], enc_f(mx));
    }

    // row softmax
    float se = 0.0f;
#pragma unroll
    for (int m = 0; m < 64; ++m) { s[m] = __expf(s[m] - v1); se += s[m]; }
    float inv = 1.0f / se;
#pragma unroll
    for (int j = 0; j < 16; ++j) {
        float4 t = make_float4(s[4 * j] * inv, s[4 * j + 1] * inv,
                               s[4 * j + 2] * inv, s[4 * j + 3] * inv);
        ((float4*)(out_sm + (size_t)row * 64))[j] = t;
    }

    g_top1[row] = i1;
    g_top2i[row] = i2;
}

// ---------------- K2: column sums of exp(s - cmax) ----------------------------
__global__ __launch_bounds__(256) void k2_colsum() {
    __shared__ float cm[64];
    __shared__ float red[256];
    int tid = threadIdx.x;
    if (tid < 64) cm[tid] = dec_f(g_cmax_u[tid]);
    __syncthreads();
    int m = tid & 63;
    float cmx = cm[m];
    float part = 0.0f;
    for (int i = blockIdx.x * 256 + tid; i < ROWS * M; i += 128 * 256)
        part += __expf(g_score[i] - cmx);
    red[tid] = part;
    __syncthreads();
    if (tid < 64) {
        float ssum = red[tid] + red[tid + 64] + red[tid + 128] + red[tid + 192];
        atomicAdd(&g_csum[tid], ssum);
    }
}

// ---------------- K3: write score_query ---------------------------------------
__global__ __launch_bounds__(256) void k3_sq(float* __restrict__ out_sq) {
    __shared__ float cm[64], iv[64];
    int tid = threadIdx.x;
    if (tid < 64) { cm[tid] = dec_f(g_cmax_u[tid]); iv[tid] = 1.0f / g_csum[tid]; }
    __syncthreads();
    const float4* src = (const float4*)g_score;
    float4* dst = (float4*)out_sq;
    for (int i4 = blockIdx.x * 256 + tid; i4 < (ROWS * M) / 4; i4 += 256 * 256) {
        int m0 = (i4 << 2) & 63;
        float4 v = src[i4];
        float4 o;
        o.x = __expf(v.x - cm[m0])     * iv[m0];
        o.y = __expf(v.y - cm[m0 + 1]) * iv[m0 + 1];
        o.z = __expf(v.z - cm[m0 + 2]) * iv[m0 + 2];
        o.w = __expf(v.w - cm[m0 + 3]) * iv[m0 + 3];
        dst[i4] = o;
    }
}

// ---------------- K4: query copy + gathering + spreading (32-row tiles) -------
__global__ __launch_bounds__(256) void k4_gl(const float* __restrict__ q,
                                             const float* __restrict__ keys,
                                             float* __restrict__ out_uq,
                                             float* __restrict__ out_gl,
                                             float* __restrict__ out_sp) {
    __shared__ float tile[256 * 33];
    __shared__ int gi[32], gi2[32];
    __shared__ float wdp[8 * 32], wdn[8 * 32];

    const int tid = threadIdx.x;
    const int row0 = blockIdx.x * 32;
    if (tid < 32) { gi[tid] = g_top1[row0 + tid]; gi2[tid] = g_top2i[row0 + tid]; }
    __syncthreads();

    // phase A: coalesced load, write updated_query[:256] copy, stage transpose
    {
        const int r = tid & 31, dg = tid >> 5;
#pragma unroll 4
        for (int it = 0; it < 32; ++it) {
            int d = it * 8 + dg;
            float qv = q[(size_t)d * ROWS + row0 + r];
            out_uq[(size_t)d * ROWS + row0 + r] = qv;
            tile[d * 33 + r] = qv;
        }
    }
    __syncthreads();

    // phase B: per-row compute, d fast across threads
    const int lane = tid & 31, w = tid >> 5;
    const int d = tid;
    for (int it = 0; it < 32; ++it) {
        int g = gi[it], g2 = gi2[it];
        float qv = tile[d * 33 + it];
        float kp = __ldg(&keys[g * 256 + d]);
        float kn = __ldg(&keys[g2 * 256 + d]);
        float df = qv - kp;
        out_gl[(size_t)(row0 + it) * 256 + d] = df * df;
        float a = df + 1e-6f;
        float b = qv - kn + 1e-6f;
        float dp = a * a, dn = b * b;
#pragma unroll
        for (int off = 16; off > 0; off >>= 1) {
            dp += __shfl_xor_sync(0xffffffffu, dp, off);
            dn += __shfl_xor_sync(0xffffffffu, dn, off);
        }
        if (lane == 0) { wdp[w * 32 + it] = dp; wdn[w * 32 + it] = dn; }
    }
    __syncthreads();
    if (tid < 32) {
        float dps = 0.0f, dns = 0.0f;
#pragma unroll
        for (int ww = 0; ww < 8; ++ww) { dps += wdp[ww * 32 + tid]; dns += wdn[ww * 32 + tid]; }
        out_sp[row0 + tid] = fmaxf(sqrtf(dps) - sqrtf(dns) + 1.0f, 0.0f);
    }
}

// ---------------- K5: concat_memory GEMM, write updated_query[256:] -----------
__global__ __launch_bounds__(256) void k5_cm(const float* __restrict__ sm,
                                             float* __restrict__ out_uq) {
    const int row = blockIdx.x * 256 + threadIdx.x;

    float p[64];
#pragma unroll
    for (int j = 0; j < 16; ++j) {
        float4 t = ((const float4*)(sm + (size_t)row * 64))[j];
        p[4 * j] = t.x; p[4 * j + 1] = t.y; p[4 * j + 2] = t.z; p[4 * j + 3] = t.w;
    }
    ull p2[32];
#pragma unroll
    for (int j = 0; j < 32; ++j) p2[j] = pack2(p[2 * j], p[2 * j + 1]);

    const ulonglong2* ks2 = (const ulonglong2*)g_keysT;
#pragma unroll 2
    for (int d = 0; d < D; ++d) {
        ull a0 = 0ull, a1 = 0ull;
#pragma unroll
        for (int jj = 0; jj < 16; ++jj) {
            ulonglong2 kk = __ldg(&ks2[d * 16 + jj]);
            a0 = fma2(p2[2 * jj],     kk.x, a0);
            a1 = fma2(p2[2 * jj + 1], kk.y, a1);
        }
        float l0, h0, l1, h1;
        unpack2(a0, l0, h0); unpack2(a1, l1, h1);
        out_uq[(size_t)(256 + d) * ROWS + row] = (l0 + h0) + (l1 + h1);
    }
}

// ---------------- K6: query_update scatter-reduce ------------------------------
__global__ __launch_bounds__(256) void k6_qu(const float* __restrict__ q) {
    __shared__ float acc[64 * 129];   // padded: bank = (g+d)%32, conflict-free
    __shared__ float cmx[64];
    const int tid = threadIdx.x;
    const int row = blockIdx.x * 256 + tid;
    if (tid < 64) cmx[tid] = dec_f(g_cmax_u[tid]);
    __syncthreads();

    const int g = g_top1[row];
    const float wgt = __expf(g_score[(size_t)row * 64 + g] - cmx[g]);

    for (int half = 0; half < 2; ++half) {
        for (int i = tid; i < 64 * 129; i += 256) acc[i] = 0.0f;
        __syncthreads();
        const int dbase = half * 128;
#pragma unroll 4
        for (int dd = 0; dd < 128; ++dd) {
            float qv = q[(size_t)(dbase + dd) * ROWS + row];
            atomicAdd(&acc[g * 129 + dd], wgt * qv);
        }
        __syncthreads();
        for (int i = tid; i < 64 * 128; i += 256) {
            int m = i >> 7, dd = i & 127;
            atomicAdd(&g_qupd[m * 256 + dbase + dd], acc[m * 129 + dd]);
        }
        __syncthreads();
    }
}

// ---------------- K7: updated_memory = normalize(qupd + keys) -----------------
__global__ __launch_bounds__(256) void k7_um(const float* __restrict__ keys,
                                             float* __restrict__ out_um) {
    __shared__ float wr[8];
    const int m = blockIdx.x, d = threadIdx.x;
    const int lane = d & 31, w = d >> 5;
    float val = g_qupd[m * 256 + d] + keys[m * 256 + d];
    float ss = val * val;
#pragma unroll
    for (int off = 16; off > 0; off >>= 1) ss += __shfl_xor_sync(0xffffffffu, ss, off);
    if (lane == 0) wr[w] = ss;
    __syncthreads();
    float tot = 0.0f;
#pragma unroll
    for (int i = 0; i < 8; ++i) tot += wr[i];
    float n = sqrtf(tot);
    float denom = fmaxf(n, 1e-12f);
    out_um[m * 256 + d] = val / denom;
}

// ---------------- launch -------------------------------------------------------
extern "C" void kernel_launch(void* const* d_in, const int* in_sizes, int n_in,
                              void* d_out, int out_size) {
    const float* query = (const float*)d_in[0];   // (256, 1024, 64)
    const float* keys  = (const float*)d_in[1];   // (64, 256)
    float* out = (float*)d_out;

    k0_init<<<64, 256>>>(keys);
    k1_score<<<256, 256>>>(query, out + OFF_SM);
    k2_colsum<<<128, 256>>>();
    k3_sq<<<256, 256>>>(out + OFF_SQ);
    k4_gl<<<2048, 256>>>(query, keys, out + OFF_UQ, out + OFF_GL, out + OFF_SP);
    k5_cm<<<256, 256>>>(out + OFF_SM, out + OFF_UQ);
    k6_qu<<<256, 256>>>(query);
    k7_um<<<64, 256>>>(keys, out + OFF_UM);
}

// round 5
// speedup vs baseline: 1.4825x; 1.4825x over previous
#include <cuda_runtime.h>
#include <math.h>

#define D 256
#define T_ 1024
#define NN 64
#define ROWS 65536   // T_*NN
#define M 64

// output layout (concatenated, fp32)
#define OFF_UQ 0UL                  // (512,1024,64) = 33554432
#define OFF_UM 33554432UL           // (64,256)      = 16384
#define OFF_SQ 33570816UL           // (65536,64)    = 4194304
#define OFF_SM 37765120UL           // (65536,64)    = 4194304
#define OFF_SP 41959424UL           // (65536,)      = 65536
#define OFF_GL 42024960UL           // (65536,256)   = 16777216

typedef unsigned long long ull;

// ---------------- scratch (static device globals; no allocations) ------------
__device__ float g_score[ROWS * M];     // raw scores, 16 MB
__device__ float g_keysT[D * M];        // keys transposed [d][m]
__device__ float g_bmax[256 * M];       // per-block column max partials
__device__ float g_bsum[256 * M];       // per-block column sum partials (vs bmax)
__device__ float g_cmax[M];
__device__ float g_csum[M];
__device__ float g_sval[ROWS];          // row max = score at top1
__device__ int   g_top1[ROWS];
__device__ int   g_top2i[ROWS];
__device__ float g_qupd[M * D];

// ---------------- helpers ----------------------------------------------------
__device__ __forceinline__ ull pack2(float lo, float hi) {
    ull r; asm("mov.b64 %0, {%1, %2};" : "=l"(r) : "f"(lo), "f"(hi)); return r;
}
__device__ __forceinline__ void unpack2(ull v, float& lo, float& hi) {
    asm("mov.b64 {%0, %1}, %2;" : "=f"(lo), "=f"(hi) : "l"(v));
}
__device__ __forceinline__ ull fma2(ull a, ull b, ull c) {
    ull d; asm("fma.rn.f32x2 %0, %1, %2, %3;" : "=l"(d) : "l"(a), "l"(b), "l"(c));
    return d;
}

// ---------------- K0: init + keys transpose -----------------------------------
__global__ void k0_init(const float* __restrict__ keys) {
    int i = blockIdx.x * 256 + threadIdx.x;   // 64*256 = 16384 threads
    int m = i >> 8, d = i & 255;
    g_keysT[d * M + m] = keys[i];
    g_qupd[i] = 0.0f;
}

// ---------------- K1: score GEMM + row softmax + top2 + col partials ----------
__global__ __launch_bounds__(256) void k1_score(const float* __restrict__ q,
                                                float* __restrict__ out_sm) {
    __shared__ float sK[D * M];        // 64 KB keysT [d][m]
    __shared__ float wred[8 * 64];
    __shared__ float bmaxs[64];
    const int tid = threadIdx.x;
    const int row = blockIdx.x * 256 + tid;
    const int lane = tid & 31, wid = tid >> 5;

    {   // stage keysT to SMEM (coalesced)
        const float4* src = (const float4*)g_keysT;
        float4* dst = (float4*)sK;
#pragma unroll
        for (int i = 0; i < 16; ++i) dst[i * 256 + tid] = src[i * 256 + tid];
    }
    __syncthreads();

    ull acc[32];
#pragma unroll
    for (int j = 0; j < 32; ++j) acc[j] = 0ull;

    const ulonglong2* ks2 = (const ulonglong2*)sK;

    for (int d0 = 0; d0 < D; d0 += 8) {
        float qv[8];
#pragma unroll
        for (int u = 0; u < 8; ++u) qv[u] = __ldg(&q[(d0 + u) * ROWS + row]);
#pragma unroll
        for (int u = 0; u < 8; ++u) {
            ull q2 = pack2(qv[u], qv[u]);
#pragma unroll
            for (int jj = 0; jj < 16; ++jj) {
                ulonglong2 kk = ks2[(d0 + u) * 16 + jj];
                acc[2 * jj]     = fma2(q2, kk.x, acc[2 * jj]);
                acc[2 * jj + 1] = fma2(q2, kk.y, acc[2 * jj + 1]);
            }
        }
    }

    float s[64];
#pragma unroll
    for (int j = 0; j < 32; ++j) unpack2(acc[j], s[2 * j], s[2 * j + 1]);

    // raw scores to scratch
#pragma unroll
    for (int j = 0; j < 16; ++j) {
        float4 t = make_float4(s[4 * j], s[4 * j + 1], s[4 * j + 2], s[4 * j + 3]);
        ((float4*)(g_score + (size_t)row * 64))[j] = t;
    }

    // top-2 (strict > keeps lowest index on ties, matching lax.top_k)
    float v1 = -1e30f, v2 = -1e30f; int i1 = 0, i2 = 0;
#pragma unroll
    for (int m = 0; m < 64; ++m) {
        float v = s[m];
        if (v > v1) { v2 = v1; i2 = i1; v1 = v; i1 = m; }
        else if (v > v2) { v2 = v; i2 = m; }
    }
    g_top1[row] = i1;
    g_top2i[row] = i2;
    g_sval[row] = v1;

    // block column-max partials
#pragma unroll
    for (int m = 0; m < 64; ++m) {
        float v = s[m];
        v = fmaxf(v, __shfl_xor_sync(0xffffffffu, v, 16));
        v = fmaxf(v, __shfl_xor_sync(0xffffffffu, v, 8));
        v = fmaxf(v, __shfl_xor_sync(0xffffffffu, v, 4));
        v = fmaxf(v, __shfl_xor_sync(0xffffffffu, v, 2));
        v = fmaxf(v, __shfl_xor_sync(0xffffffffu, v, 1));
        if (lane == 0) wred[wid * 64 + m] = v;
    }
    __syncthreads();
    if (tid < 64) {
        float mx = wred[tid];
#pragma unroll
        for (int w = 1; w < 8; ++w) mx = fmaxf(mx, wred[w * 64 + tid]);
        bmaxs[tid] = mx;
        g_bmax[blockIdx.x * 64 + tid] = mx;
    }
    __syncthreads();

    // block column-sum partials w.r.t. block max (online softmax merge later)
#pragma unroll
    for (int m = 0; m < 64; ++m) {
        float c = __expf(s[m] - bmaxs[m]);
        c += __shfl_xor_sync(0xffffffffu, c, 16);
        c += __shfl_xor_sync(0xffffffffu, c, 8);
        c += __shfl_xor_sync(0xffffffffu, c, 4);
        c += __shfl_xor_sync(0xffffffffu, c, 2);
        c += __shfl_xor_sync(0xffffffffu, c, 1);
        if (lane == 0) wred[wid * 64 + m] = c;
    }
    __syncthreads();
    if (tid < 64) {
        float sm = 0.0f;
#pragma unroll
        for (int w = 0; w < 8; ++w) sm += wred[w * 64 + tid];
        g_bsum[blockIdx.x * 64 + tid] = sm;
    }

    // row softmax
    float se = 0.0f;
#pragma unroll
    for (int m = 0; m < 64; ++m) { s[m] = __expf(s[m] - v1); se += s[m]; }
    float inv = 1.0f / se;
#pragma unroll
    for (int j = 0; j < 16; ++j) {
        float4 t = make_float4(s[4 * j] * inv, s[4 * j + 1] * inv,
                               s[4 * j + 2] * inv, s[4 * j + 3] * inv);
        ((float4*)(out_sm + (size_t)row * 64))[j] = t;
    }
}

// ---------------- K2: combine per-block partials ------------------------------
__global__ __launch_bounds__(256) void k2_combine() {   // grid 64 (one per m)
    __shared__ float red[256];
    const int m = blockIdx.x, t = threadIdx.x;
    float bm = g_bmax[t * 64 + m];
    red[t] = bm;
    __syncthreads();
#pragma unroll
    for (int s = 128; s > 0; s >>= 1) {
        if (t < s) red[t] = fmaxf(red[t], red[t + s]);
        __syncthreads();
    }
    float cmax = red[0];
    __syncthreads();
    red[t] = g_bsum[t * 64 + m] * __expf(bm - cmax);
    __syncthreads();
#pragma unroll
    for (int s = 128; s > 0; s >>= 1) {
        if (t < s) red[t] += red[t + s];
        __syncthreads();
    }
    if (t == 0) { g_cmax[m] = cmax; g_csum[m] = red[0]; }
}

// ---------------- K3: write score_query ---------------------------------------
__global__ __launch_bounds__(256) void k3_sq(float* __restrict__ out_sq) {
    __shared__ float cm[64], iv[64];
    const int tid = threadIdx.x;
    if (tid < 64) { cm[tid] = g_cmax[tid]; iv[tid] = 1.0f / g_csum[tid]; }
    __syncthreads();
    const float4* src = (const float4*)g_score;
    float4* dst = (float4*)out_sq;
    const int base = blockIdx.x * 256 + tid;   // grid 1024 -> 262144 threads
#pragma unroll
    for (int r = 0; r < 4; ++r) {
        int i4 = base + r * 262144;
        int m0 = (i4 << 2) & 63;
        float4 v = src[i4];
        float4 o;
        o.x = __expf(v.x - cm[m0])     * iv[m0];
        o.y = __expf(v.y - cm[m0 + 1]) * iv[m0 + 1];
        o.z = __expf(v.z - cm[m0 + 2]) * iv[m0 + 2];
        o.w = __expf(v.w - cm[m0 + 3]) * iv[m0 + 3];
        dst[i4] = o;
    }
}

// ---------------- K4: query copy + gathering + spreading (32-row tiles) -------
__global__ __launch_bounds__(256) void k4_gl(const float* __restrict__ q,
                                             const float* __restrict__ keys,
                                             float* __restrict__ out_uq,
                                             float* __restrict__ out_gl,
                                             float* __restrict__ out_sp) {
    __shared__ float tile[256 * 33];
    __shared__ int gi[32], gi2[32];
    __shared__ float wdp[8 * 32], wdn[8 * 32];

    const int tid = threadIdx.x;
    const int row0 = blockIdx.x * 32;
    if (tid < 32) { gi[tid] = g_top1[row0 + tid]; gi2[tid] = g_top2i[row0 + tid]; }
    __syncthreads();

    // phase A: coalesced load, write updated_query[:256] copy, stage transpose
    {
        const int r = tid & 31, dg = tid >> 5;
#pragma unroll 8
        for (int it = 0; it < 32; ++it) {
            int d = it * 8 + dg;
            float qv = q[(size_t)d * ROWS + row0 + r];
            out_uq[(size_t)d * ROWS + row0 + r] = qv;
            tile[d * 33 + r] = qv;
        }
    }
    __syncthreads();

    // phase B: per-row compute, d fast across threads
    const int lane = tid & 31, w = tid >> 5;
    const int d = tid;
    for (int it = 0; it < 32; ++it) {
        int g = gi[it], g2 = gi2[it];
        float qv = tile[d * 33 + it];
        float kp = __ldg(&keys[g * 256 + d]);
        float kn = __ldg(&keys[g2 * 256 + d]);
        float df = qv - kp;
        out_gl[(size_t)(row0 + it) * 256 + d] = df * df;
        float a = df + 1e-6f;
        float b = qv - kn + 1e-6f;
        float dp = a * a, dn = b * b;
#pragma unroll
        for (int off = 16; off > 0; off >>= 1) {
            dp += __shfl_xor_sync(0xffffffffu, dp, off);
            dn += __shfl_xor_sync(0xffffffffu, dn, off);
        }
        if (lane == 0) { wdp[w * 32 + it] = dp; wdn[w * 32 + it] = dn; }
    }
    __syncthreads();
    if (tid < 32) {
        float dps = 0.0f, dns = 0.0f;
#pragma unroll
        for (int ww = 0; ww < 8; ++ww) { dps += wdp[ww * 32 + tid]; dns += wdn[ww * 32 + tid]; }
        out_sp[row0 + tid] = fmaxf(sqrtf(dps) - sqrtf(dns) + 1.0f, 0.0f);
    }
}

// ---------------- K5: concat_memory GEMM, write updated_query[256:] -----------
__global__ __launch_bounds__(256) void k5_cm(const float* __restrict__ sm,
                                             float* __restrict__ out_uq) {
    __shared__ float sK[D * M];        // 64 KB keysT [d][m]
    const int tid = threadIdx.x;
    const int row = blockIdx.x * 256 + tid;

    {
        const float4* src = (const float4*)g_keysT;
        float4* dst = (float4*)sK;
#pragma unroll
        for (int i = 0; i < 16; ++i) dst[i * 256 + tid] = src[i * 256 + tid];
    }
    __syncthreads();

    float p[64];
#pragma unroll
    for (int j = 0; j < 16; ++j) {
        float4 t = __ldg(&((const float4*)(sm + (size_t)row * 64))[j]);
        p[4 * j] = t.x; p[4 * j + 1] = t.y; p[4 * j + 2] = t.z; p[4 * j + 3] = t.w;
    }
    ull p2[32];
#pragma unroll
    for (int j = 0; j < 32; ++j) p2[j] = pack2(p[2 * j], p[2 * j + 1]);

    const ulonglong2* ks2 = (const ulonglong2*)sK;
#pragma unroll 4
    for (int d = 0; d < D; ++d) {
        ull a0 = 0ull, a1 = 0ull;
#pragma unroll
        for (int jj = 0; jj < 16; ++jj) {
            ulonglong2 kk = ks2[d * 16 + jj];
            a0 = fma2(p2[2 * jj],     kk.x, a0);
            a1 = fma2(p2[2 * jj + 1], kk.y, a1);
        }
        float l0, h0, l1, h1;
        unpack2(a0, l0, h0); unpack2(a1, l1, h1);
        out_uq[(size_t)(256 + d) * ROWS + row] = (l0 + h0) + (l1 + h1);
    }
}

// ---------------- K6: query_update scatter-reduce ------------------------------
__global__ __launch_bounds__(256) void k6_qu(const float* __restrict__ q) {
    __shared__ float acc[64 * 129];   // padded: bank = (g+d)%32, conflict-free
    __shared__ float cmx[64];
    const int tid = threadIdx.x;
    const int row = blockIdx.x * 256 + tid;
    if (tid < 64) cmx[tid] = g_cmax[tid];
    __syncthreads();

    const int g = g_top1[row];
    const float wgt = __expf(g_sval[row] - cmx[g]);

    for (int half = 0; half < 2; ++half) {
        for (int i = tid; i < 64 * 129; i += 256) acc[i] = 0.0f;
        __syncthreads();
        const int dbase = half * 128;
#pragma unroll 8
        for (int dd = 0; dd < 128; ++dd) {
            float qv = q[(size_t)(dbase + dd) * ROWS + row];
            atomicAdd(&acc[g * 129 + dd], wgt * qv);
        }
        __syncthreads();
        for (int i = tid; i < 64 * 128; i += 256) {
            int m = i >> 7, dd = i & 127;
            atomicAdd(&g_qupd[m * 256 + dbase + dd], acc[m * 129 + dd]);
        }
        __syncthreads();
    }
}

// ---------------- K7: updated_memory = normalize(qupd + keys) -----------------
__global__ __launch_bounds__(256) void k7_um(const float* __restrict__ keys,
                                             float* __restrict__ out_um) {
    __shared__ float wr[8];
    const int m = blockIdx.x, d = threadIdx.x;
    const int lane = d & 31, w = d >> 5;
    float val = g_qupd[m * 256 + d] + keys[m * 256 + d];
    float ss = val * val;
#pragma unroll
    for (int off = 16; off > 0; off >>= 1) ss += __shfl_xor_sync(0xffffffffu, ss, off);
    if (lane == 0) wr[w] = ss;
    __syncthreads();
    float tot = 0.0f;
#pragma unroll
    for (int i = 0; i < 8; ++i) tot += wr[i];
    float n = sqrtf(tot);
    float denom = fmaxf(n, 1e-12f);
    out_um[m * 256 + d] = val / denom;
}

// ---------------- launch -------------------------------------------------------
extern "C" void kernel_launch(void* const* d_in, const int* in_sizes, int n_in,
                              void* d_out, int out_size) {
    const float* query = (const float*)d_in[0];   // (256, 1024, 64)
    const float* keys  = (const float*)d_in[1];   // (64, 256)
    float* out = (float*)d_out;

    k0_init<<<64, 256>>>(keys);
    k1_score<<<256, 256>>>(query, out + OFF_SM);
    k2_combine<<<64, 256>>>();
    k3_sq<<<1024, 256>>>(out + OFF_SQ);
    k4_gl<<<2048, 256>>>(query, keys, out + OFF_UQ, out + OFF_GL, out + OFF_SP);
    k5_cm<<<256, 256>>>(out + OFF_SM, out + OFF_UQ);
    k6_qu<<<256, 256>>>(query);
    k7_um<<<64, 256>>>(keys, out + OFF_UM);
}

// round 6
// speedup vs baseline: 1.9451x; 1.3120x over previous
#include <cuda_runtime.h>
#include <math.h>

#define D 256
#define T_ 1024
#define NN 64
#define ROWS 65536   // T_*NN
#define M 64

// output layout (concatenated, fp32)
#define OFF_UQ 0UL                  // (512,1024,64) = 33554432
#define OFF_UM 33554432UL           // (64,256)      = 16384
#define OFF_SQ 33570816UL           // (65536,64)    = 4194304
#define OFF_SM 37765120UL           // (65536,64)    = 4194304
#define OFF_SP 41959424UL           // (65536,)      = 65536
#define OFF_GL 42024960UL           // (65536,256)   = 16777216

typedef unsigned long long ull;

// ---------------- scratch (static device globals; no allocations) ------------
__device__ float g_score[ROWS * M];     // raw scores, 16 MB
__device__ float g_keysT[D * M];        // keys transposed [d][m]
__device__ float g_bmax[256 * M];       // per-block column max partials
__device__ float g_bsum[256 * M];       // per-block column sum partials (vs bmax)
__device__ float g_cmax[M];
__device__ float g_csum[M];
__device__ float g_sval[ROWS];          // row max = score at top1
__device__ int   g_top1[ROWS];
__device__ int   g_top2i[ROWS];
__device__ float g_qupd[M * D];

// ---------------- helpers ----------------------------------------------------
__device__ __forceinline__ ull pack2(float lo, float hi) {
    ull r; asm("mov.b64 %0, {%1, %2};" : "=l"(r) : "f"(lo), "f"(hi)); return r;
}
__device__ __forceinline__ void unpack2(ull v, float& lo, float& hi) {
    asm("mov.b64 {%0, %1}, %2;" : "=f"(lo), "=f"(hi) : "l"(v));
}
__device__ __forceinline__ ull fma2(ull a, ull b, ull c) {
    ull d; asm("fma.rn.f32x2 %0, %1, %2, %3;" : "=l"(d) : "l"(a), "l"(b), "l"(c));
    return d;
}

// ---------------- K0: init + keys transpose -----------------------------------
__global__ void k0_init(const float* __restrict__ keys) {
    int i = blockIdx.x * 256 + threadIdx.x;   // 64*256 = 16384 threads
    int m = i >> 8, d = i & 255;
    g_keysT[d * M + m] = keys[i];
    g_qupd[i] = 0.0f;
}

// ---------------- K1: score GEMM + row softmax + top2 + col partials + uq copy
__global__ __launch_bounds__(256) void k1_score(const float* __restrict__ q,
                                                float* __restrict__ out_sm,
                                                float* __restrict__ out_uq) {
    __shared__ float sK[D * M];        // 64 KB keysT [d][m]
    __shared__ float wred[8 * 64];
    __shared__ float bmaxs[64];
    const int tid = threadIdx.x;
    const int row = blockIdx.x * 256 + tid;
    const int lane = tid & 31, wid = tid >> 5;

    {   // stage keysT to SMEM (coalesced)
        const float4* src = (const float4*)g_keysT;
        float4* dst = (float4*)sK;
#pragma unroll
        for (int i = 0; i < 16; ++i) dst[i * 256 + tid] = src[i * 256 + tid];
    }
    __syncthreads();

    ull acc[32];
#pragma unroll
    for (int j = 0; j < 32; ++j) acc[j] = 0ull;

    const ulonglong2* ks2 = (const ulonglong2*)sK;

    for (int d0 = 0; d0 < D; d0 += 8) {
        float qv[8];
#pragma unroll
        for (int u = 0; u < 8; ++u) qv[u] = __ldg(&q[(d0 + u) * ROWS + row]);
#pragma unroll
        for (int u = 0; u < 8; ++u)        // free updated_query[:256] copy
            out_uq[(size_t)(d0 + u) * ROWS + row] = qv[u];
#pragma unroll
        for (int u = 0; u < 8; ++u) {
            ull q2 = pack2(qv[u], qv[u]);
#pragma unroll
            for (int jj = 0; jj < 16; ++jj) {
                ulonglong2 kk = ks2[(d0 + u) * 16 + jj];
                acc[2 * jj]     = fma2(q2, kk.x, acc[2 * jj]);
                acc[2 * jj + 1] = fma2(q2, kk.y, acc[2 * jj + 1]);
            }
        }
    }

    float s[64];
#pragma unroll
    for (int j = 0; j < 32; ++j) unpack2(acc[j], s[2 * j], s[2 * j + 1]);

    // raw scores to scratch
#pragma unroll
    for (int j = 0; j < 16; ++j) {
        float4 t = make_float4(s[4 * j], s[4 * j + 1], s[4 * j + 2], s[4 * j + 3]);
        ((float4*)(g_score + (size_t)row * 64))[j] = t;
    }

    // top-2 (strict > keeps lowest index on ties, matching lax.top_k)
    float v1 = -1e30f, v2 = -1e30f; int i1 = 0, i2 = 0;
#pragma unroll
    for (int m = 0; m < 64; ++m) {
        float v = s[m];
        if (v > v1) { v2 = v1; i2 = i1; v1 = v; i1 = m; }
        else if (v > v2) { v2 = v; i2 = m; }
    }
    g_top1[row] = i1;
    g_top2i[row] = i2;
    g_sval[row] = v1;

    // block column-max partials
#pragma unroll
    for (int m = 0; m < 64; ++m) {
        float v = s[m];
        v = fmaxf(v, __shfl_xor_sync(0xffffffffu, v, 16));
        v = fmaxf(v, __shfl_xor_sync(0xffffffffu, v, 8));
        v = fmaxf(v, __shfl_xor_sync(0xffffffffu, v, 4));
        v = fmaxf(v, __shfl_xor_sync(0xffffffffu, v, 2));
        v = fmaxf(v, __shfl_xor_sync(0xffffffffu, v, 1));
        if (lane == 0) wred[wid * 64 + m] = v;
    }
    __syncthreads();
    if (tid < 64) {
        float mx = wred[tid];
#pragma unroll
        for (int w = 1; w < 8; ++w) mx = fmaxf(mx, wred[w * 64 + tid]);
        bmaxs[tid] = mx;
        g_bmax[blockIdx.x * 64 + tid] = mx;
    }
    __syncthreads();

    // block column-sum partials w.r.t. block max (online softmax merge later)
#pragma unroll
    for (int m = 0; m < 64; ++m) {
        float c = __expf(s[m] - bmaxs[m]);
        c += __shfl_xor_sync(0xffffffffu, c, 16);
        c += __shfl_xor_sync(0xffffffffu, c, 8);
        c += __shfl_xor_sync(0xffffffffu, c, 4);
        c += __shfl_xor_sync(0xffffffffu, c, 2);
        c += __shfl_xor_sync(0xffffffffu, c, 1);
        if (lane == 0) wred[wid * 64 + m] = c;
    }
    __syncthreads();
    if (tid < 64) {
        float sm = 0.0f;
#pragma unroll
        for (int w = 0; w < 8; ++w) sm += wred[w * 64 + tid];
        g_bsum[blockIdx.x * 64 + tid] = sm;
    }

    // row softmax
    float se = 0.0f;
#pragma unroll
    for (int m = 0; m < 64; ++m) { s[m] = __expf(s[m] - v1); se += s[m]; }
    float inv = 1.0f / se;
#pragma unroll
    for (int j = 0; j < 16; ++j) {
        float4 t = make_float4(s[4 * j] * inv, s[4 * j + 1] * inv,
                               s[4 * j + 2] * inv, s[4 * j + 3] * inv);
        ((float4*)(out_sm + (size_t)row * 64))[j] = t;
    }
}

// ---------------- K2: combine per-block partials ------------------------------
__global__ __launch_bounds__(256) void k2_combine() {   // grid 64 (one per m)
    __shared__ float red[256];
    const int m = blockIdx.x, t = threadIdx.x;
    float bm = g_bmax[t * 64 + m];
    red[t] = bm;
    __syncthreads();
#pragma unroll
    for (int s = 128; s > 0; s >>= 1) {
        if (t < s) red[t] = fmaxf(red[t], red[t + s]);
        __syncthreads();
    }
    float cmax = red[0];
    __syncthreads();
    red[t] = g_bsum[t * 64 + m] * __expf(bm - cmax);
    __syncthreads();
#pragma unroll
    for (int s = 128; s > 0; s >>= 1) {
        if (t < s) red[t] += red[t + s];
        __syncthreads();
    }
    if (t == 0) { g_cmax[m] = cmax; g_csum[m] = red[0]; }
}

// ---------------- K3: write score_query ---------------------------------------
__global__ __launch_bounds__(256) void k3_sq(float* __restrict__ out_sq) {
    __shared__ float cm[64], iv[64];
    const int tid = threadIdx.x;
    if (tid < 64) { cm[tid] = g_cmax[tid]; iv[tid] = 1.0f / g_csum[tid]; }
    __syncthreads();
    const float4* src = (const float4*)g_score;
    float4* dst = (float4*)out_sq;
    const int base = blockIdx.x * 256 + tid;   // grid 1024 -> 262144 threads
#pragma unroll
    for (int r = 0; r < 4; ++r) {
        int i4 = base + r * 262144;
        int m0 = (i4 << 2) & 63;
        float4 v = src[i4];
        float4 o;
        o.x = __expf(v.x - cm[m0])     * iv[m0];
        o.y = __expf(v.y - cm[m0 + 1]) * iv[m0 + 1];
        o.z = __expf(v.z - cm[m0 + 2]) * iv[m0 + 2];
        o.w = __expf(v.w - cm[m0 + 3]) * iv[m0 + 3];
        dst[i4] = o;
    }
}

// ---------------- K4f: gathering + spreading + query_update scatter (fused) ---
// block = 256 rows in 8 chunks of 32; thread owns (m = tid>>2, dgrp = tid&3)
// with 64 d's (d = dgrp + 4*i) for the register-accumulated scatter-reduce.
__global__ __launch_bounds__(256) void k4_fused(const float* __restrict__ q,
                                                const float* __restrict__ keys,
                                                float* __restrict__ out_gl,
                                                float* __restrict__ out_sp) {
    __shared__ float tile[256 * 33];   // [d][r]
    __shared__ int   gi[32], gi2[32];
    __shared__ float swgt[32];
    __shared__ float wdp[8 * 32], wdn[8 * 32];
    __shared__ float scm[64];

    const int tid = threadIdx.x;
    const int lane = tid & 31, w = tid >> 5;
    const int m_own = tid >> 2, dgrp = tid & 3;
    const int rowbase = blockIdx.x * 256;

    if (tid < 64) scm[tid] = g_cmax[tid];

    float acc[64];
#pragma unroll
    for (int i = 0; i < 64; ++i) acc[i] = 0.0f;

    for (int c = 0; c < 8; ++c) {
        const int row0 = rowbase + c * 32;
        __syncthreads();   // previous chunk's readers done; scm ready (c==0)
        if (tid < 32) {
            int g = g_top1[row0 + tid];
            gi[tid] = g;
            gi2[tid] = g_top2i[row0 + tid];
            swgt[tid] = __expf(g_sval[row0 + tid] - scm[g]);
        }
        // phase A: coalesced load of 32x256 q chunk into [d][r] tile
        {
            const int r = tid & 31, dg = tid >> 5;
#pragma unroll 8
            for (int it = 0; it < 32; ++it) {
                int d = it * 8 + dg;
                tile[d * 33 + r] = q[(size_t)d * ROWS + row0 + r];
            }
        }
        __syncthreads();

        // phase B: gathering_loss + triplet distances (d = tid across threads)
        const int d = tid;
        for (int it = 0; it < 32; ++it) {
            int g = gi[it], g2 = gi2[it];
            float qv = tile[d * 33 + it];
            float kp = __ldg(&keys[g * 256 + d]);
            float kn = __ldg(&keys[g2 * 256 + d]);
            float df = qv - kp;
            out_gl[(size_t)(row0 + it) * 256 + d] = df * df;
            float a = df + 1e-6f;
            float b = qv - kn + 1e-6f;
            float dp = a * a, dn = b * b;
#pragma unroll
            for (int off = 16; off > 0; off >>= 1) {
                dp += __shfl_xor_sync(0xffffffffu, dp, off);
                dn += __shfl_xor_sync(0xffffffffu, dn, off);
            }
            if (lane == 0) { wdp[w * 32 + it] = dp; wdn[w * 32 + it] = dn; }
        }

        // phase C: scatter-reduce into registers (4 matching lanes per row)
        for (int r = 0; r < 32; ++r) {
            if (m_own == gi[r]) {
                float wv = swgt[r];
#pragma unroll
                for (int i = 0; i < 64; ++i)
                    acc[i] += wv * tile[(dgrp + 4 * i) * 33 + r];
            }
        }
        __syncthreads();
        if (tid < 32) {
            float dps = 0.0f, dns = 0.0f;
#pragma unroll
            for (int ww = 0; ww < 8; ++ww) { dps += wdp[ww * 32 + tid]; dns += wdn[ww * 32 + tid]; }
            out_sp[row0 + tid] = fmaxf(sqrtf(dps) - sqrtf(dns) + 1.0f, 0.0f);
        }
    }

    // epilogue: one global reduce per (m, d)
#pragma unroll
    for (int i = 0; i < 64; ++i)
        atomicAdd(&g_qupd[m_own * 256 + dgrp + 4 * i], acc[i]);
}

// ---------------- K5: concat_memory GEMM, write updated_query[256:] -----------
__global__ __launch_bounds__(256) void k5_cm(const float* __restrict__ sm,
                                             float* __restrict__ out_uq) {
    __shared__ float sK[D * M];        // 64 KB keysT [d][m]
    const int tid = threadIdx.x;
    const int row = blockIdx.x * 256 + tid;

    {
        const float4* src = (const float4*)g_keysT;
        float4* dst = (float4*)sK;
#pragma unroll
        for (int i = 0; i < 16; ++i) dst[i * 256 + tid] = src[i * 256 + tid];
    }
    __syncthreads();

    float p[64];
#pragma unroll
    for (int j = 0; j < 16; ++j) {
        float4 t = __ldg(&((const float4*)(sm + (size_t)row * 64))[j]);
        p[4 * j] = t.x; p[4 * j + 1] = t.y; p[4 * j + 2] = t.z; p[4 * j + 3] = t.w;
    }
    ull p2[32];
#pragma unroll
    for (int j = 0; j < 32; ++j) p2[j] = pack2(p[2 * j], p[2 * j + 1]);

    const ulonglong2* ks2 = (const ulonglong2*)sK;
#pragma unroll 4
    for (int d = 0; d < D; ++d) {
        ull a0 = 0ull, a1 = 0ull;
#pragma unroll
        for (int jj = 0; jj < 16; ++jj) {
            ulonglong2 kk = ks2[d * 16 + jj];
            a0 = fma2(p2[2 * jj],     kk.x, a0);
            a1 = fma2(p2[2 * jj + 1], kk.y, a1);
        }
        float l0, h0, l1, h1;
        unpack2(a0, l0, h0); unpack2(a1, l1, h1);
        out_uq[(size_t)(256 + d) * ROWS + row] = (l0 + h0) + (l1 + h1);
    }
}

// ---------------- K7: updated_memory = normalize(qupd + keys) -----------------
__global__ __launch_bounds__(256) void k7_um(const float* __restrict__ keys,
                                             float* __restrict__ out_um) {
    __shared__ float wr[8];
    const int m = blockIdx.x, d = threadIdx.x;
    const int lane = d & 31, w = d >> 5;
    float val = g_qupd[m * 256 + d] + keys[m * 256 + d];
    float ss = val * val;
#pragma unroll
    for (int off = 16; off > 0; off >>= 1) ss += __shfl_xor_sync(0xffffffffu, ss, off);
    if (lane == 0) wr[w] = ss;
    __syncthreads();
    float tot = 0.0f;
#pragma unroll
    for (int i = 0; i < 8; ++i) tot += wr[i];
    float n = sqrtf(tot);
    float denom = fmaxf(n, 1e-12f);
    out_um[m * 256 + d] = val / denom;
}

// ---------------- launch -------------------------------------------------------
extern "C" void kernel_launch(void* const* d_in, const int* in_sizes, int n_in,
                              void* d_out, int out_size) {
    const float* query = (const float*)d_in[0];   // (256, 1024, 64)
    const float* keys  = (const float*)d_in[1];   // (64, 256)
    float* out = (float*)d_out;

    k0_init<<<64, 256>>>(keys);
    k1_score<<<256, 256>>>(query, out + OFF_SM, out + OFF_UQ);
    k2_combine<<<64, 256>>>();
    k3_sq<<<1024, 256>>>(out + OFF_SQ);
    k5_cm<<<256, 256>>>(out + OFF_SM, out + OFF_UQ);
    k4_fused<<<256, 256>>>(query, keys, out + OFF_GL, out + OFF_SP);
    k7_um<<<64, 256>>>(keys, out + OFF_UM);
}

// round 7
// speedup vs baseline: 2.0011x; 1.0288x over previous
#include <cuda_runtime.h>
#include <math.h>

#define D 256
#define T_ 1024
#define NN 64
#define ROWS 65536   // T_*NN
#define M 64

// output layout (concatenated, fp32)
#define OFF_UQ 0UL                  // (512,1024,64) = 33554432
#define OFF_UM 33554432UL           // (64,256)      = 16384
#define OFF_SQ 33570816UL           // (65536,64)    = 4194304
#define OFF_SM 37765120UL           // (65536,64)    = 4194304
#define OFF_SP 41959424UL           // (65536,)      = 65536
#define OFF_GL 42024960UL           // (65536,256)   = 16777216

typedef unsigned long long ull;

// ---------------- scratch (static device globals; no allocations) ------------
__device__ float g_score[ROWS * M];     // raw scores, 16 MB
__device__ float g_keysT[D * M];        // keys transposed [d][m]
__device__ float g_bmax[256 * M];       // per-block column max partials
__device__ float g_bsum[256 * M];       // per-block column sum partials (vs bmax)
__device__ float g_cmax[M];
__device__ float g_csum[M];
__device__ float g_sval[ROWS];          // row max = score at top1
__device__ int   g_top1[ROWS];
__device__ int   g_top2i[ROWS];
__device__ float g_qupd[M * D];

// ---------------- helpers ----------------------------------------------------
__device__ __forceinline__ ull pack2(float lo, float hi) {
    ull r; asm("mov.b64 %0, {%1, %2};" : "=l"(r) : "f"(lo), "f"(hi)); return r;
}
__device__ __forceinline__ void unpack2(ull v, float& lo, float& hi) {
    asm("mov.b64 {%0, %1}, %2;" : "=f"(lo), "=f"(hi) : "l"(v));
}
__device__ __forceinline__ ull fma2(ull a, ull b, ull c) {
    ull d; asm("fma.rn.f32x2 %0, %1, %2, %3;" : "=l"(d) : "l"(a), "l"(b), "l"(c));
    return d;
}

// ---------------- K0: init + keys transpose -----------------------------------
__global__ void k0_init(const float* __restrict__ keys) {
    int i = blockIdx.x * 256 + threadIdx.x;   // 64*256 = 16384 threads
    int m = i >> 8, d = i & 255;
    g_keysT[d * M + m] = keys[i];
    g_qupd[i] = 0.0f;
}

// ---------------- K1: score GEMM + softmaxes + top2 + concat GEMM (fused) -----
__global__ __launch_bounds__(256) void k1_score(const float* __restrict__ q,
                                                float* __restrict__ out_sm,
                                                float* __restrict__ out_uq) {
    __shared__ float sK[D * M];        // 64 KB keysT [d][m]
    __shared__ float wred[8 * 64];
    __shared__ float bmaxs[64];
    const int tid = threadIdx.x;
    const int row = blockIdx.x * 256 + tid;
    const int lane = tid & 31, wid = tid >> 5;

    {   // stage keysT to SMEM (coalesced)
        const float4* src = (const float4*)g_keysT;
        float4* dst = (float4*)sK;
#pragma unroll
        for (int i = 0; i < 16; ++i) dst[i * 256 + tid] = src[i * 256 + tid];
    }
    __syncthreads();

    ull acc[32];
#pragma unroll
    for (int j = 0; j < 32; ++j) acc[j] = 0ull;

    const ulonglong2* ks2 = (const ulonglong2*)sK;

    for (int d0 = 0; d0 < D; d0 += 8) {
        float qv[8];
#pragma unroll
        for (int u = 0; u < 8; ++u) qv[u] = __ldg(&q[(d0 + u) * ROWS + row]);
#pragma unroll
        for (int u = 0; u < 8; ++u)        // free updated_query[:256] copy
            out_uq[(size_t)(d0 + u) * ROWS + row] = qv[u];
#pragma unroll
        for (int u = 0; u < 8; ++u) {
            ull q2 = pack2(qv[u], qv[u]);
#pragma unroll
            for (int jj = 0; jj < 16; ++jj) {
                ulonglong2 kk = ks2[(d0 + u) * 16 + jj];
                acc[2 * jj]     = fma2(q2, kk.x, acc[2 * jj]);
                acc[2 * jj + 1] = fma2(q2, kk.y, acc[2 * jj + 1]);
            }
        }
    }

    float s[64];
#pragma unroll
    for (int j = 0; j < 32; ++j) unpack2(acc[j], s[2 * j], s[2 * j + 1]);

    // raw scores to scratch
#pragma unroll
    for (int j = 0; j < 16; ++j) {
        float4 t = make_float4(s[4 * j], s[4 * j + 1], s[4 * j + 2], s[4 * j + 3]);
        ((float4*)(g_score + (size_t)row * 64))[j] = t;
    }

    // top-2 (strict > keeps lowest index on ties, matching lax.top_k)
    float v1 = -1e30f, v2 = -1e30f; int i1 = 0, i2 = 0;
#pragma unroll
    for (int m = 0; m < 64; ++m) {
        float v = s[m];
        if (v > v1) { v2 = v1; i2 = i1; v1 = v; i1 = m; }
        else if (v > v2) { v2 = v; i2 = m; }
    }
    g_top1[row] = i1;
    g_top2i[row] = i2;
    g_sval[row] = v1;

    // block column-max partials
#pragma unroll
    for (int m = 0; m < 64; ++m) {
        float v = s[m];
        v = fmaxf(v, __shfl_xor_sync(0xffffffffu, v, 16));
        v = fmaxf(v, __shfl_xor_sync(0xffffffffu, v, 8));
        v = fmaxf(v, __shfl_xor_sync(0xffffffffu, v, 4));
        v = fmaxf(v, __shfl_xor_sync(0xffffffffu, v, 2));
        v = fmaxf(v, __shfl_xor_sync(0xffffffffu, v, 1));
        if (lane == 0) wred[wid * 64 + m] = v;
    }
    __syncthreads();
    if (tid < 64) {
        float mx = wred[tid];
#pragma unroll
        for (int w = 1; w < 8; ++w) mx = fmaxf(mx, wred[w * 64 + tid]);
        bmaxs[tid] = mx;
        g_bmax[blockIdx.x * 64 + tid] = mx;
    }
    __syncthreads();

    // block column-sum partials w.r.t. block max (online softmax merge later)
#pragma unroll
    for (int m = 0; m < 64; ++m) {
        float c = __expf(s[m] - bmaxs[m]);
        c += __shfl_xor_sync(0xffffffffu, c, 16);
        c += __shfl_xor_sync(0xffffffffu, c, 8);
        c += __shfl_xor_sync(0xffffffffu, c, 4);
        c += __shfl_xor_sync(0xffffffffu, c, 2);
        c += __shfl_xor_sync(0xffffffffu, c, 1);
        if (lane == 0) wred[wid * 64 + m] = c;
    }
    __syncthreads();
    if (tid < 64) {
        float sm = 0.0f;
#pragma unroll
        for (int w = 0; w < 8; ++w) sm += wred[w * 64 + tid];
        g_bsum[blockIdx.x * 64 + tid] = sm;
    }

    // row softmax -> probabilities (== score_memory row)
    float se = 0.0f;
#pragma unroll
    for (int m = 0; m < 64; ++m) { s[m] = __expf(s[m] - v1); se += s[m]; }
    float inv = 1.0f / se;
#pragma unroll
    for (int m = 0; m < 64; ++m) s[m] *= inv;
#pragma unroll
    for (int j = 0; j < 16; ++j) {
        float4 t = make_float4(s[4 * j], s[4 * j + 1], s[4 * j + 2], s[4 * j + 3]);
        ((float4*)(out_sm + (size_t)row * 64))[j] = t;
    }

    // ---- fused concat_memory GEMM: updated_query[256:] = P @ keys ----
    ull p2[32];
#pragma unroll
    for (int j = 0; j < 32; ++j) p2[j] = pack2(s[2 * j], s[2 * j + 1]);

#pragma unroll 4
    for (int d = 0; d < D; ++d) {
        ull a0 = 0ull, a1 = 0ull;
#pragma unroll
        for (int jj = 0; jj < 16; ++jj) {
            ulonglong2 kk = ks2[d * 16 + jj];
            a0 = fma2(p2[2 * jj],     kk.x, a0);
            a1 = fma2(p2[2 * jj + 1], kk.y, a1);
        }
        float l0, h0, l1, h1;
        unpack2(a0, l0, h0); unpack2(a1, l1, h1);
        out_uq[(size_t)(256 + d) * ROWS + row] = (l0 + h0) + (l1 + h1);
    }
}

// ---------------- K2: combine per-block partials ------------------------------
__global__ __launch_bounds__(256) void k2_combine() {   // grid 64 (one per m)
    __shared__ float red[256];
    const int m = blockIdx.x, t = threadIdx.x;
    float bm = g_bmax[t * 64 + m];
    red[t] = bm;
    __syncthreads();
#pragma unroll
    for (int s = 128; s > 0; s >>= 1) {
        if (t < s) red[t] = fmaxf(red[t], red[t + s]);
        __syncthreads();
    }
    float cmax = red[0];
    __syncthreads();
    red[t] = g_bsum[t * 64 + m] * __expf(bm - cmax);
    __syncthreads();
#pragma unroll
    for (int s = 128; s > 0; s >>= 1) {
        if (t < s) red[t] += red[t + s];
        __syncthreads();
    }
    if (t == 0) { g_cmax[m] = cmax; g_csum[m] = red[0]; }
}

// ---------------- K3: write score_query ---------------------------------------
__global__ __launch_bounds__(256) void k3_sq(float* __restrict__ out_sq) {
    __shared__ float cm[64], iv[64];
    const int tid = threadIdx.x;
    if (tid < 64) { cm[tid] = g_cmax[tid]; iv[tid] = 1.0f / g_csum[tid]; }
    __syncthreads();
    const float4* src = (const float4*)g_score;
    float4* dst = (float4*)out_sq;
    const int base = blockIdx.x * 256 + tid;   // grid 1024 -> 262144 threads
#pragma unroll
    for (int r = 0; r < 4; ++r) {
        int i4 = base + r * 262144;
        int m0 = (i4 << 2) & 63;
        float4 v = src[i4];
        float4 o;
        o.x = __expf(v.x - cm[m0])     * iv[m0];
        o.y = __expf(v.y - cm[m0 + 1]) * iv[m0 + 1];
        o.z = __expf(v.z - cm[m0 + 2]) * iv[m0 + 2];
        o.w = __expf(v.w - cm[m0 + 3]) * iv[m0 + 3];
        dst[i4] = o;
    }
}

// ---------------- K4f: gathering + spreading + query_update scatter (fused) ---
// warp w owns memories [8w, 8w+8); lane covers d = lane + 32*i (i<8).
// Ownership test is warp-uniform -> no divergence waste in phase C.
__global__ __launch_bounds__(256) void k4_fused(const float* __restrict__ q,
                                                const float* __restrict__ keys,
                                                float* __restrict__ out_gl,
                                                float* __restrict__ out_sp) {
    __shared__ float tile[256 * 33];   // [d][r]
    __shared__ int   gi[32], gi2[32];
    __shared__ float swgt[32];
    __shared__ float wdp[8 * 32], wdn[8 * 32];
    __shared__ float scm[64];

    const int tid = threadIdx.x;
    const int lane = tid & 31, w = tid >> 5;
    const int rowbase = blockIdx.x * 256;

    if (tid < 64) scm[tid] = g_cmax[tid];

    float acc[8][8];   // [mi][i]
#pragma unroll
    for (int mi = 0; mi < 8; ++mi)
#pragma unroll
        for (int i = 0; i < 8; ++i) acc[mi][i] = 0.0f;

    for (int c = 0; c < 8; ++c) {
        const int row0 = rowbase + c * 32;
        __syncthreads();   // previous chunk's readers done; scm ready (c==0)
        if (tid < 32) {
            int g = g_top1[row0 + tid];
            gi[tid] = g;
            gi2[tid] = g_top2i[row0 + tid];
            swgt[tid] = __expf(g_sval[row0 + tid] - scm[g]);
        }
        // phase A: coalesced load of 32x256 q chunk into [d][r] tile
        {
            const int r = lane, dg = w;
#pragma unroll 8
            for (int it = 0; it < 32; ++it) {
                int d = it * 8 + dg;
                tile[d * 33 + r] = q[(size_t)d * ROWS + row0 + r];
            }
        }
        __syncthreads();

        // phase B: gathering_loss + triplet distances (d = tid across threads)
        const int d = tid;
        for (int it = 0; it < 32; ++it) {
            int g = gi[it], g2 = gi2[it];
            float qv = tile[d * 33 + it];
            float kp = __ldg(&keys[g * 256 + d]);
            float kn = __ldg(&keys[g2 * 256 + d]);
            float df = qv - kp;
            out_gl[(size_t)(row0 + it) * 256 + d] = df * df;
            float a = df + 1e-6f;
            float b = qv - kn + 1e-6f;
            float dp = a * a, dn = b * b;
#pragma unroll
            for (int off = 16; off > 0; off >>= 1) {
                dp += __shfl_xor_sync(0xffffffffu, dp, off);
                dn += __shfl_xor_sync(0xffffffffu, dn, off);
            }
            if (lane == 0) { wdp[w * 32 + it] = dp; wdn[w * 32 + it] = dn; }
        }

        // phase C: warp-owned scatter-reduce into registers
        for (int r = 0; r < 32; ++r) {
            int g = gi[r];
            if ((g >> 3) == w) {
                float wv = swgt[r];
#pragma unroll
                for (int mi = 0; mi < 8; ++mi) {
                    if (g == w * 8 + mi) {
#pragma unroll
                        for (int i = 0; i < 8; ++i)
                            acc[mi][i] += wv * tile[(lane + 32 * i) * 33 + r];
                    }
                }
            }
        }
        __syncthreads();
        if (tid < 32) {
            float dps = 0.0f, dns = 0.0f;
#pragma unroll
            for (int ww = 0; ww < 8; ++ww) { dps += wdp[ww * 32 + tid]; dns += wdn[ww * 32 + tid]; }
            out_sp[row0 + tid] = fmaxf(sqrtf(dps) - sqrtf(dns) + 1.0f, 0.0f);
        }
    }

    // epilogue: one global reduce per (m, d)
#pragma unroll
    for (int mi = 0; mi < 8; ++mi)
#pragma unroll
        for (int i = 0; i < 8; ++i)
            atomicAdd(&g_qupd[(w * 8 + mi) * 256 + lane + 32 * i], acc[mi][i]);
}

// ---------------- K7: updated_memory = normalize(qupd + keys) -----------------
__global__ __launch_bounds__(256) void k7_um(const float* __restrict__ keys,
                                             float* __restrict__ out_um) {
    __shared__ float wr[8];
    const int m = blockIdx.x, d = threadIdx.x;
    const int lane = d & 31, w = d >> 5;
    float val = g_qupd[m * 256 + d] + keys[m * 256 + d];
    float ss = val * val;
#pragma unroll
    for (int off = 16; off > 0; off >>= 1) ss += __shfl_xor_sync(0xffffffffu, ss, off);
    if (lane == 0) wr[w] = ss;
    __syncthreads();
    float tot = 0.0f;
#pragma unroll
    for (int i = 0; i < 8; ++i) tot += wr[i];
    float n = sqrtf(tot);
    float denom = fmaxf(n, 1e-12f);
    out_um[m * 256 + d] = val / denom;
}

// ---------------- launch -------------------------------------------------------
extern "C" void kernel_launch(void* const* d_in, const int* in_sizes, int n_in,
                              void* d_out, int out_size) {
    const float* query = (const float*)d_in[0];   // (256, 1024, 64)
    const float* keys  = (const float*)d_in[1];   // (64, 256)
    float* out = (float*)d_out;

    k0_init<<<64, 256>>>(keys);
    k1_score<<<256, 256>>>(query, out + OFF_SM, out + OFF_UQ);
    k2_combine<<<64, 256>>>();
    k3_sq<<<1024, 256>>>(out + OFF_SQ);
    k4_fused<<<256, 256>>>(query, keys, out + OFF_GL, out + OFF_SP);
    k7_um<<<64, 256>>>(keys, out + OFF_UM);
}

// round 11
// speedup vs baseline: 2.4366x; 1.2176x over previous
#include <cuda_runtime.h>
#include <math.h>
#include <cstdint>

#define D 256
#define T_ 1024
#define NN 64
#define ROWS 65536   // T_*NN
#define M 64

// output layout (concatenated, fp32)
#define OFF_UQ 0UL                  // (512,1024,64) = 33554432
#define OFF_UM 33554432UL           // (64,256)      = 16384
#define OFF_SQ 33570816UL           // (65536,64)    = 4194304
#define OFF_SM 37765120UL           // (65536,64)    = 4194304
#define OFF_SP 41959424UL           // (65536,)      = 65536
#define OFF_GL 42024960UL           // (65536,256)   = 16777216

typedef unsigned long long ull;

// ---------------- scratch (static device globals; no allocations) ------------
__device__ float g_keysT[D * M];        // keys transposed [d][m]
__device__ float g_knorm[M];            // ||k_m||^2
__device__ float g_ksum[M];             // sum_d k_m[d]
__device__ float g_bmax[256 * M];       // per-block column max partials
__device__ float g_bsum[256 * M];       // per-block column sum partials (vs bmax)
__device__ float g_cmax[M];
__device__ float g_csum[M];
__device__ float g_sval[ROWS];          // row max = score at top1
__device__ float g_se[ROWS];            // row sum of exp(s - rowmax)
__device__ int   g_top1[ROWS];
__device__ int   g_top2i[ROWS];
__device__ float g_qupd[M * D];

// ---------------- scalar helpers ---------------------------------------------
__device__ __forceinline__ ull pack2(float lo, float hi) {
    ull r; asm("mov.b64 %0, {%1, %2};" : "=l"(r) : "f"(lo), "f"(hi)); return r;
}
__device__ __forceinline__ void unpack2(ull v, float& lo, float& hi) {
    asm("mov.b64 {%0, %1}, %2;" : "=f"(lo), "=f"(hi) : "l"(v));
}
__device__ __forceinline__ ull fma2(ull a, ull b, ull c) {
    ull d; asm("fma.rn.f32x2 %0, %1, %2, %3;" : "=l"(d) : "l"(a), "l"(b), "l"(c));
    return d;
}

// ---------------- K0: init + keys transpose + key norms/sums -------------------
__global__ __launch_bounds__(256) void k0_init(const float* __restrict__ keys) {
    __shared__ float rn[8], rs[8];
    const int b = blockIdx.x;          // memory slot m
    const int t = threadIdx.x;         // d
    const int lane = t & 31, w = t >> 5;
    float kv = keys[b * 256 + t];
    g_keysT[t * M + b] = kv;
    g_qupd[b * 256 + t] = 0.0f;
    float n2 = kv * kv, sm = kv;
#pragma unroll
    for (int off = 16; off > 0; off >>= 1) {
        n2 += __shfl_xor_sync(0xffffffffu, n2, off);
        sm += __shfl_xor_sync(0xffffffffu, sm, off);
    }
    if (lane == 0) { rn[w] = n2; rs[w] = sm; }
    __syncthreads();
    if (t == 0) {
        float tn = 0.0f, ts = 0.0f;
#pragma unroll
        for (int i = 0; i < 8; ++i) { tn += rn[i]; ts += rs[i]; }
        g_knorm[b] = tn;
        g_ksum[b] = ts;
    }
}

// ---------------- K1: score GEMM + softmaxes + top2 + spreading + concat GEMM -
__global__ __launch_bounds__(256) void k1_score(const float* __restrict__ q,
                                                float* __restrict__ out_sm,
                                                float* __restrict__ out_uq,
                                                float* __restrict__ out_sp) {
    __shared__ float sK[D * M];        // 64 KB keysT [d][m]
    __shared__ float wred[8 * 64];
    __shared__ float bmaxs[64];
    __shared__ float sKn[64], sKs[64];
    const int tid = threadIdx.x;
    const int row = blockIdx.x * 256 + tid;
    const int lane = tid & 31, wid = tid >> 5;

    {   // stage keysT to SMEM (coalesced)
        const float4* src = (const float4*)g_keysT;
        float4* dst = (float4*)sK;
#pragma unroll
        for (int i = 0; i < 16; ++i) dst[i * 256 + tid] = src[i * 256 + tid];
        if (tid < 64) { sKn[tid] = g_knorm[tid]; sKs[tid] = g_ksum[tid]; }
    }
    __syncthreads();

    ull acc[32];
#pragma unroll
    for (int j = 0; j < 32; ++j) acc[j] = 0ull;
    float nq2 = 0.0f, sumq = 0.0f;

    const ulonglong2* ks2 = (const ulonglong2*)sK;

    for (int d0 = 0; d0 < D; d0 += 8) {
        float qv[8];
#pragma unroll
        for (int u = 0; u < 8; ++u) qv[u] = __ldg(&q[(d0 + u) * ROWS + row]);
#pragma unroll
        for (int u = 0; u < 8; ++u) {      // free updated_query[:256] copy
            out_uq[(size_t)(d0 + u) * ROWS + row] = qv[u];
            nq2 = fmaf(qv[u], qv[u], nq2);
            sumq += qv[u];
        }
#pragma unroll
        for (int u = 0; u < 8; ++u) {
            ull q2 = pack2(qv[u], qv[u]);
#pragma unroll
            for (int jj = 0; jj < 16; ++jj) {
                ulonglong2 kk = ks2[(d0 + u) * 16 + jj];
                acc[2 * jj]     = fma2(q2, kk.x, acc[2 * jj]);
                acc[2 * jj + 1] = fma2(q2, kk.y, acc[2 * jj + 1]);
            }
        }
    }

    float s[64];
#pragma unroll
    for (int j = 0; j < 32; ++j) unpack2(acc[j], s[2 * j], s[2 * j + 1]);

    // top-2 (strict > keeps lowest index on ties, matching lax.top_k)
    float v1 = -1e30f, v2 = -1e30f; int i1 = 0, i2 = 0;
#pragma unroll
    for (int m = 0; m < 64; ++m) {
        float v = s[m];
        if (v > v1) { v2 = v1; i2 = i1; v1 = v; i1 = m; }
        else if (v > v2) { v2 = v; i2 = m; }
    }
    g_top1[row] = i1;
    g_top2i[row] = i2;
    g_sval[row] = v1;

    // spreading_loss via algebraic identity:
    // ||q - k + e||^2 = ||q||^2 - 2 s + ||k||^2 + 2e(sum q - sum k) + 256 e^2
    {
        const float e = 1e-6f;
        float dp2 = nq2 - 2.0f * v1 + sKn[i1] + 2.0f * e * (sumq - sKs[i1]) + 256.0f * e * e;
        float dn2 = nq2 - 2.0f * v2 + sKn[i2] + 2.0f * e * (sumq - sKs[i2]) + 256.0f * e * e;
        out_sp[row] = fmaxf(sqrtf(fmaxf(dp2, 0.0f)) - sqrtf(fmaxf(dn2, 0.0f)) + 1.0f, 0.0f);
    }

    // block column-max partials
#pragma unroll
    for (int m = 0; m < 64; ++m) {
        float v = s[m];
        v = fmaxf(v, __shfl_xor_sync(0xffffffffu, v, 16));
        v = fmaxf(v, __shfl_xor_sync(0xffffffffu, v, 8));
        v = fmaxf(v, __shfl_xor_sync(0xffffffffu, v, 4));
        v = fmaxf(v, __shfl_xor_sync(0xffffffffu, v, 2));
        v = fmaxf(v, __shfl_xor_sync(0xffffffffu, v, 1));
        if (lane == 0) wred[wid * 64 + m] = v;
    }
    __syncthreads();
    if (tid < 64) {
        float mx = wred[tid];
#pragma unroll
        for (int w = 1; w < 8; ++w) mx = fmaxf(mx, wred[w * 64 + tid]);
        bmaxs[tid] = mx;
        g_bmax[blockIdx.x * 64 + tid] = mx;
    }
    __syncthreads();

    // block column-sum partials w.r.t. block max (online softmax merge later)
#pragma unroll
    for (int m = 0; m < 64; ++m) {
        float c = __expf(s[m] - bmaxs[m]);
        c += __shfl_xor_sync(0xffffffffu, c, 16);
        c += __shfl_xor_sync(0xffffffffu, c, 8);
        c += __shfl_xor_sync(0xffffffffu, c, 4);
        c += __shfl_xor_sync(0xffffffffu, c, 2);
        c += __shfl_xor_sync(0xffffffffu, c, 1);
        if (lane == 0) wred[wid * 64 + m] = c;
    }
    __syncthreads();
    if (tid < 64) {
        float sm = 0.0f;
#pragma unroll
        for (int w = 0; w < 8; ++w) sm += wred[w * 64 + tid];
        g_bsum[blockIdx.x * 64 + tid] = sm;
    }

    // row softmax -> probabilities (== score_memory row)
    float se = 0.0f;
#pragma unroll
    for (int m = 0; m < 64; ++m) { s[m] = __expf(s[m] - v1); se += s[m]; }
    g_se[row] = se;
    float inv = 1.0f / se;
#pragma unroll
    for (int m = 0; m < 64; ++m) s[m] *= inv;
#pragma unroll
    for (int j = 0; j < 16; ++j) {
        float4 t = make_float4(s[4 * j], s[4 * j + 1], s[4 * j + 2], s[4 * j + 3]);
        ((float4*)(out_sm + (size_t)row * 64))[j] = t;
    }

    // ---- fused concat_memory GEMM: updated_query[256:] = P @ keys ----
    ull p2[32];
#pragma unroll
    for (int j = 0; j < 32; ++j) p2[j] = pack2(s[2 * j], s[2 * j + 1]);

#pragma unroll 4
    for (int d = 0; d < D; ++d) {
        ull a0 = 0ull, a1 = 0ull;
#pragma unroll
        for (int jj = 0; jj < 16; ++jj) {
            ulonglong2 kk = ks2[d * 16 + jj];
            a0 = fma2(p2[2 * jj],     kk.x, a0);
            a1 = fma2(p2[2 * jj + 1], kk.y, a1);
        }
        float l0, h0, l1, h1;
        unpack2(a0, l0, h0); unpack2(a1, l1, h1);
        out_uq[(size_t)(256 + d) * ROWS + row] = (l0 + h0) + (l1 + h1);
    }
}

// ---------------- K2: combine per-block partials ------------------------------
__global__ __launch_bounds__(256) void k2_combine() {   // grid 64 (one per m)
    __shared__ float red[256];
    const int m = blockIdx.x, t = threadIdx.x;
    float bm = g_bmax[t * 64 + m];
    red[t] = bm;
    __syncthreads();
#pragma unroll
    for (int s = 128; s > 0; s >>= 1) {
        if (t < s) red[t] = fmaxf(red[t], red[t + s]);
        __syncthreads();
    }
    float cmax = red[0];
    __syncthreads();
    red[t] = g_bsum[t * 64 + m] * __expf(bm - cmax);
    __syncthreads();
#pragma unroll
    for (int s = 128; s > 0; s >>= 1) {
        if (t < s) red[t] += red[t + s];
        __syncthreads();
    }
    if (t == 0) { g_cmax[m] = cmax; g_csum[m] = red[0]; }
}

// ---------------- K3: score_query reconstructed from score_memory -------------
// sq[r][m] = sm[r][m] * se_r * exp(v1_r - cmax_m) / csum_m
__global__ __launch_bounds__(256) void k3_sq(const float* __restrict__ sm_in,
                                             float* __restrict__ out_sq) {
    __shared__ float cm[64], iv[64];
    const int tid = threadIdx.x;
    if (tid < 64) { cm[tid] = g_cmax[tid]; iv[tid] = 1.0f / g_csum[tid]; }
    __syncthreads();
    const float4* src = (const float4*)sm_in;
    float4* dst = (float4*)out_sq;
    const int base = blockIdx.x * 256 + tid;   // grid 1024 -> 262144 threads
#pragma unroll
    for (int r = 0; r < 4; ++r) {
        int i4 = base + r * 262144;
        int row = i4 >> 4;
        float v1 = __ldg(&g_sval[row]);
        float se = __ldg(&g_se[row]);
        int m0 = (i4 << 2) & 63;
        float4 v = src[i4];
        float4 o;
        o.x = v.x * se * __expf(v1 - cm[m0])     * iv[m0];
        o.y = v.y * se * __expf(v1 - cm[m0 + 1]) * iv[m0 + 1];
        o.z = v.z * se * __expf(v1 - cm[m0 + 2]) * iv[m0 + 2];
        o.w = v.w * se * __expf(v1 - cm[m0 + 3]) * iv[m0 + 3];
        dst[i4] = o;
    }
}

// ---------------- K4f: gathering_loss + query_update scatter (fused) ----------
// warp w owns memories [8w, 8w+8); lane covers d = lane + 32*i (i<8).
__global__ __launch_bounds__(256) void k4_fused(const float* __restrict__ q,
                                                const float* __restrict__ keys,
                                                float* __restrict__ out_gl) {
    __shared__ float tile[256 * 33];   // [d][r]
    __shared__ int   gi[32];
    __shared__ float swgt[32];
    __shared__ float scm[64];

    const int tid = threadIdx.x;
    const int lane = tid & 31, w = tid >> 5;
    const int rowbase = blockIdx.x * 256;

    if (tid < 64) scm[tid] = g_cmax[tid];

    float acc[8][8];   // [mi][i]
#pragma unroll
    for (int mi = 0; mi < 8; ++mi)
#pragma unroll
        for (int i = 0; i < 8; ++i) acc[mi][i] = 0.0f;

    for (int c = 0; c < 8; ++c) {
        const int row0 = rowbase + c * 32;
        __syncthreads();   // previous chunk's readers done; scm ready (c==0)
        if (tid < 32) {
            int g = g_top1[row0 + tid];
            gi[tid] = g;
            swgt[tid] = __expf(g_sval[row0 + tid] - scm[g]);
        }
        // phase A: coalesced load of 32x256 q chunk into [d][r] tile
        {
            const int r = lane, dg = w;
#pragma unroll 8
            for (int it = 0; it < 32; ++it) {
                int d = it * 8 + dg;
                tile[d * 33 + r] = q[(size_t)d * ROWS + row0 + r];
            }
        }
        __syncthreads();

        // phase B: gathering_loss only (d = tid across threads, coalesced)
        const int d = tid;
#pragma unroll 4
        for (int it = 0; it < 32; ++it) {
            int g = gi[it];
            float qv = tile[d * 33 + it];
            float kp = __ldg(&keys[g * 256 + d]);
            float df = qv - kp;
            out_gl[(size_t)(row0 + it) * 256 + d] = df * df;
        }

        // phase C: warp-owned scatter-reduce into registers
        for (int r = 0; r < 32; ++r) {
            int g = gi[r];
            if ((g >> 3) == w) {
                float wv = swgt[r];
#pragma unroll
                for (int mi = 0; mi < 8; ++mi) {
                    if (g == w * 8 + mi) {
#pragma unroll
                        for (int i = 0; i < 8; ++i)
                            acc[mi][i] += wv * tile[(lane + 32 * i) * 33 + r];
                    }
                }
            }
        }
    }

    // epilogue: one global reduce per (m, d)
#pragma unroll
    for (int mi = 0; mi < 8; ++mi)
#pragma unroll
        for (int i = 0; i < 8; ++i)
            atomicAdd(&g_qupd[(w * 8 + mi) * 256 + lane + 32 * i], acc[mi][i]);
}

// ---------------- K7: updated_memory = normalize(qupd + keys) -----------------
__global__ __launch_bounds__(256) void k7_um(const float* __restrict__ keys,
                                             float* __restrict__ out_um) {
    __shared__ float wr[8];
    const int m = blockIdx.x, d = threadIdx.x;
    const int lane = d & 31, w = d >> 5;
    float val = g_qupd[m * 256 + d] + keys[m * 256 + d];
    float ss = val * val;
#pragma unroll
    for (int off = 16; off > 0; off >>= 1) ss += __shfl_xor_sync(0xffffffffu, ss, off);
    if (lane == 0) wr[w] = ss;
    __syncthreads();
    float tot = 0.0f;
#pragma unroll
    for (int i = 0; i < 8; ++i) tot += wr[i];
    float n = sqrtf(tot);
    float denom = fmaxf(n, 1e-12f);
    out_um[m * 256 + d] = val / denom;
}

// ---------------- launch -------------------------------------------------------
extern "C" void kernel_launch(void* const* d_in, const int* in_sizes, int n_in,
                              void* d_out, int out_size) {
    const float* query = (const float*)d_in[0];   // (256, 1024, 64)
    const float* keys  = (const float*)d_in[1];   // (64, 256)
    float* out = (float*)d_out;

    k0_init<<<64, 256>>>(keys);
    k1_score<<<256, 256>>>(query, out + OFF_SM, out + OFF_UQ, out + OFF_SP);
    k2_combine<<<64, 256>>>();
    k3_sq<<<1024, 256>>>(out + OFF_SM, out + OFF_SQ);
    k4_fused<<<256, 256>>>(query, keys, out + OFF_GL);
    k7_um<<<64, 256>>>(keys, out + OFF_UM);
}

// round 13
// speedup vs baseline: 2.6156x; 1.0735x over previous
#include <cuda_runtime.h>
#include <math.h>
#include <cstdint>

#define D 256
#define T_ 1024
#define NN 64
#define ROWS 65536   // T_*NN
#define M 64

// output layout (concatenated, fp32)
#define OFF_UQ 0UL                  // (512,1024,64) = 33554432
#define OFF_UM 33554432UL           // (64,256)      = 16384
#define OFF_SQ 33570816UL           // (65536,64)    = 4194304
#define OFF_SM 37765120UL           // (65536,64)    = 4194304
#define OFF_SP 41959424UL           // (65536,)      = 65536
#define OFF_GL 42024960UL           // (65536,256)   = 16777216

typedef unsigned long long ull;

// ---------------- scratch (static device globals; no allocations) ------------
__device__ float g_keysT[D * M];        // keys transposed [d][m]
__device__ float g_knorm[M];            // ||k_m||^2
__device__ float g_ksum[M];             // sum_d k_m[d]
__device__ float g_bmax[256 * M];       // per-block column max partials
__device__ float g_bsum[256 * M];       // per-block column sum partials (vs bmax)
__device__ float g_cmax[M];
__device__ float g_csum[M];
__device__ float g_sval[ROWS];          // row max = score at top1
__device__ float g_se[ROWS];            // row sum of exp(s - rowmax)
__device__ int   g_top1[ROWS];
__device__ int   g_top2i[ROWS];
__device__ float g_qupd[M * D];

// ---------------- scalar helpers ---------------------------------------------
__device__ __forceinline__ ull pack2(float lo, float hi) {
    ull r; asm("mov.b64 %0, {%1, %2};" : "=l"(r) : "f"(lo), "f"(hi)); return r;
}
__device__ __forceinline__ void unpack2(ull v, float& lo, float& hi) {
    asm("mov.b64 {%0, %1}, %2;" : "=f"(lo), "=f"(hi) : "l"(v));
}
__device__ __forceinline__ ull fma2(ull a, ull b, ull c) {
    ull d; asm("fma.rn.f32x2 %0, %1, %2, %3;" : "=l"(d) : "l"(a), "l"(b), "l"(c));
    return d;
}

// ---------------- K0: init + keys transpose + key norms/sums -------------------
__global__ __launch_bounds__(256) void k0_init(const float* __restrict__ keys) {
    __shared__ float rn[8], rs[8];
    const int b = blockIdx.x;          // memory slot m
    const int t = threadIdx.x;         // d
    const int lane = t & 31, w = t >> 5;
    float kv = keys[b * 256 + t];
    g_keysT[t * M + b] = kv;
    g_qupd[b * 256 + t] = 0.0f;
    float n2 = kv * kv, sm = kv;
#pragma unroll
    for (int off = 16; off > 0; off >>= 1) {
        n2 += __shfl_xor_sync(0xffffffffu, n2, off);
        sm += __shfl_xor_sync(0xffffffffu, sm, off);
    }
    if (lane == 0) { rn[w] = n2; rs[w] = sm; }
    __syncthreads();
    if (t == 0) {
        float tn = 0.0f, ts = 0.0f;
#pragma unroll
        for (int i = 0; i < 8; ++i) { tn += rn[i]; ts += rs[i]; }
        g_knorm[b] = tn;
        g_ksum[b] = ts;
    }
}

// ---------------- K1: score GEMM + softmaxes + top2 + spreading + concat GEMM -
__global__ __launch_bounds__(256, 2) void k1_score(const float* __restrict__ q,
                                                   float* __restrict__ out_sm,
                                                   float* __restrict__ out_uq,
                                                   float* __restrict__ out_sp) {
    __shared__ float sK[D * M];        // 64 KB keysT [d][m]
    __shared__ float wred[8 * 64];
    __shared__ float bmaxs[64];
    __shared__ float sKn[64], sKs[64];
    const int tid = threadIdx.x;
    const int row = blockIdx.x * 256 + tid;
    const int lane = tid & 31, wid = tid >> 5;

    {   // stage keysT to SMEM (coalesced)
        const float4* src = (const float4*)g_keysT;
        float4* dst = (float4*)sK;
#pragma unroll
        for (int i = 0; i < 16; ++i) dst[i * 256 + tid] = src[i * 256 + tid];
        if (tid < 64) { sKn[tid] = g_knorm[tid]; sKs[tid] = g_ksum[tid]; }
    }
    __syncthreads();

    ull acc[32];
#pragma unroll
    for (int j = 0; j < 32; ++j) acc[j] = 0ull;
    float nq2 = 0.0f, sumq = 0.0f;

    const ulonglong2* ks2 = (const ulonglong2*)sK;

    for (int d0 = 0; d0 < D; d0 += 8) {
        float qv[8];
#pragma unroll
        for (int u = 0; u < 8; ++u) qv[u] = __ldg(&q[(d0 + u) * ROWS + row]);
#pragma unroll
        for (int u = 0; u < 8; ++u) {      // free updated_query[:256] copy
            out_uq[(size_t)(d0 + u) * ROWS + row] = qv[u];
            nq2 = fmaf(qv[u], qv[u], nq2);
            sumq += qv[u];
        }
#pragma unroll
        for (int u = 0; u < 8; ++u) {
            ull q2 = pack2(qv[u], qv[u]);
#pragma unroll
            for (int jj = 0; jj < 16; ++jj) {
                ulonglong2 kk = ks2[(d0 + u) * 16 + jj];
                acc[2 * jj]     = fma2(q2, kk.x, acc[2 * jj]);
                acc[2 * jj + 1] = fma2(q2, kk.y, acc[2 * jj + 1]);
            }
        }
    }

    float s[64];
#pragma unroll
    for (int j = 0; j < 32; ++j) unpack2(acc[j], s[2 * j], s[2 * j + 1]);

    // top-2 (strict > keeps lowest index on ties, matching lax.top_k)
    float v1 = -1e30f, v2 = -1e30f; int i1 = 0, i2 = 0;
#pragma unroll
    for (int m = 0; m < 64; ++m) {
        float v = s[m];
        if (v > v1) { v2 = v1; i2 = i1; v1 = v; i1 = m; }
        else if (v > v2) { v2 = v; i2 = m; }
    }
    g_top1[row] = i1;
    g_top2i[row] = i2;
    g_sval[row] = v1;

    // spreading_loss via algebraic identity:
    // ||q - k + e||^2 = ||q||^2 - 2 s + ||k||^2 + 2e(sum q - sum k) + 256 e^2
    {
        const float e = 1e-6f;
        float dp2 = nq2 - 2.0f * v1 + sKn[i1] + 2.0f * e * (sumq - sKs[i1]) + 256.0f * e * e;
        float dn2 = nq2 - 2.0f * v2 + sKn[i2] + 2.0f * e * (sumq - sKs[i2]) + 256.0f * e * e;
        out_sp[row] = fmaxf(sqrtf(fmaxf(dp2, 0.0f)) - sqrtf(fmaxf(dn2, 0.0f)) + 1.0f, 0.0f);
    }

    // block column-max partials
#pragma unroll
    for (int m = 0; m < 64; ++m) {
        float v = s[m];
        v = fmaxf(v, __shfl_xor_sync(0xffffffffu, v, 16));
        v = fmaxf(v, __shfl_xor_sync(0xffffffffu, v, 8));
        v = fmaxf(v, __shfl_xor_sync(0xffffffffu, v, 4));
        v = fmaxf(v, __shfl_xor_sync(0xffffffffu, v, 2));
        v = fmaxf(v, __shfl_xor_sync(0xffffffffu, v, 1));
        if (lane == 0) wred[wid * 64 + m] = v;
    }
    __syncthreads();
    if (tid < 64) {
        float mx = wred[tid];
#pragma unroll
        for (int w = 1; w < 8; ++w) mx = fmaxf(mx, wred[w * 64 + tid]);
        bmaxs[tid] = mx;
        g_bmax[blockIdx.x * 64 + tid] = mx;
    }
    __syncthreads();

    // block column-sum partials w.r.t. block max (online softmax merge later)
#pragma unroll
    for (int m = 0; m < 64; ++m) {
        float c = __expf(s[m] - bmaxs[m]);
        c += __shfl_xor_sync(0xffffffffu, c, 16);
        c += __shfl_xor_sync(0xffffffffu, c, 8);
        c += __shfl_xor_sync(0xffffffffu, c, 4);
        c += __shfl_xor_sync(0xffffffffu, c, 2);
        c += __shfl_xor_sync(0xffffffffu, c, 1);
        if (lane == 0) wred[wid * 64 + m] = c;
    }
    __syncthreads();
    if (tid < 64) {
        float sm = 0.0f;
#pragma unroll
        for (int w = 0; w < 8; ++w) sm += wred[w * 64 + tid];
        g_bsum[blockIdx.x * 64 + tid] = sm;
    }

    // row softmax -> probabilities (== score_memory row)
    float se = 0.0f;
#pragma unroll
    for (int m = 0; m < 64; ++m) { s[m] = __expf(s[m] - v1); se += s[m]; }
    g_se[row] = se;
    float inv = 1.0f / se;
#pragma unroll
    for (int m = 0; m < 64; ++m) s[m] *= inv;
#pragma unroll
    for (int j = 0; j < 16; ++j) {
        float4 t = make_float4(s[4 * j], s[4 * j + 1], s[4 * j + 2], s[4 * j + 3]);
        ((float4*)(out_sm + (size_t)row * 64))[j] = t;
    }

    // ---- fused concat_memory GEMM: updated_query[256:] = P @ keys ----
    ull p2[32];
#pragma unroll
    for (int j = 0; j < 32; ++j) p2[j] = pack2(s[2 * j], s[2 * j + 1]);

#pragma unroll 4
    for (int d = 0; d < D; ++d) {
        ull a0 = 0ull, a1 = 0ull;
#pragma unroll
        for (int jj = 0; jj < 16; ++jj) {
            ulonglong2 kk = ks2[d * 16 + jj];
            a0 = fma2(p2[2 * jj],     kk.x, a0);
            a1 = fma2(p2[2 * jj + 1], kk.y, a1);
        }
        float l0, h0, l1, h1;
        unpack2(a0, l0, h0); unpack2(a1, l1, h1);
        out_uq[(size_t)(256 + d) * ROWS + row] = (l0 + h0) + (l1 + h1);
    }
}

// ---------------- K2: combine per-block partials ------------------------------
__global__ __launch_bounds__(256) void k2_combine() {   // grid 64 (one per m)
    __shared__ float red[256];
    const int m = blockIdx.x, t = threadIdx.x;
    float bm = g_bmax[t * 64 + m];
    red[t] = bm;
    __syncthreads();
#pragma unroll
    for (int s = 128; s > 0; s >>= 1) {
        if (t < s) red[t] = fmaxf(red[t], red[t + s]);
        __syncthreads();
    }
    float cmax = red[0];
    __syncthreads();
    red[t] = g_bsum[t * 64 + m] * __expf(bm - cmax);
    __syncthreads();
#pragma unroll
    for (int s = 128; s > 0; s >>= 1) {
        if (t < s) red[t] += red[t + s];
        __syncthreads();
    }
    if (t == 0) { g_cmax[m] = cmax; g_csum[m] = red[0]; }
}

// ---------------- K3: score_query reconstructed from score_memory -------------
// sq[r][m] = sm[r][m] * se_r * exp(v1_r - cmax_m) / csum_m
__global__ __launch_bounds__(256) void k3_sq(const float* __restrict__ sm_in,
                                             float* __restrict__ out_sq) {
    __shared__ float cm[64], iv[64];
    const int tid = threadIdx.x;
    if (tid < 64) { cm[tid] = g_cmax[tid]; iv[tid] = 1.0f / g_csum[tid]; }
    __syncthreads();
    const float4* src = (const float4*)sm_in;
    float4* dst = (float4*)out_sq;
    const int base = blockIdx.x * 256 + tid;   // grid 1024 -> 262144 threads
#pragma unroll
    for (int r = 0; r < 4; ++r) {
        int i4 = base + r * 262144;
        int row = i4 >> 4;
        float v1 = __ldg(&g_sval[row]);
        float se = __ldg(&g_se[row]);
        int m0 = (i4 << 2) & 63;
        float4 v = src[i4];
        float4 o;
        o.x = v.x * se * __expf(v1 - cm[m0])     * iv[m0];
        o.y = v.y * se * __expf(v1 - cm[m0 + 1]) * iv[m0 + 1];
        o.z = v.z * se * __expf(v1 - cm[m0 + 2]) * iv[m0 + 2];
        o.w = v.w * se * __expf(v1 - cm[m0 + 3]) * iv[m0 + 3];
        dst[i4] = o;
    }
}

// ---------------- K4f: gathering_loss + query_update scatter (fused) ----------
// grid 512 x 128 rows; warp w owns memories [8w, 8w+8); lane covers d = lane+32i.
__global__ __launch_bounds__(256, 2) void k4_fused(const float* __restrict__ q,
                                                   const float* __restrict__ keys,
                                                   float* __restrict__ out_gl) {
    __shared__ float tile[256 * 33];   // [d][r]
    __shared__ int   gi[32];
    __shared__ float swgt[32];
    __shared__ float scm[64];

    const int tid = threadIdx.x;
    const int lane = tid & 31, w = tid >> 5;
    const int rowbase = blockIdx.x * 128;

    if (tid < 64) scm[tid] = g_cmax[tid];

    float acc[8][8];   // [mi][i]
#pragma unroll
    for (int mi = 0; mi < 8; ++mi)
#pragma unroll
        for (int i = 0; i < 8; ++i) acc[mi][i] = 0.0f;

    for (int c = 0; c < 4; ++c) {
        const int row0 = rowbase + c * 32;
        __syncthreads();   // previous chunk's readers done; scm ready (c==0)
        if (tid < 32) {
            int g = g_top1[row0 + tid];
            gi[tid] = g;
            swgt[tid] = __expf(g_sval[row0 + tid] - scm[g]);
        }
        // phase A: coalesced load of 32x256 q chunk into [d][r] tile
        {
            const int r = lane, dg = w;
#pragma unroll 8
            for (int it = 0; it < 32; ++it) {
                int d = it * 8 + dg;
                tile[d * 33 + r] = q[(size_t)d * ROWS + row0 + r];
            }
        }
        __syncthreads();

        // phase B: gathering_loss only (d = tid across threads, coalesced)
        const int d = tid;
#pragma unroll 4
        for (int it = 0; it < 32; ++it) {
            int g = gi[it];
            float qv = tile[d * 33 + it];
            float kp = __ldg(&keys[g * 256 + d]);
            float df = qv - kp;
            out_gl[(size_t)(row0 + it) * 256 + d] = df * df;
        }

        // phase C: warp-owned scatter-reduce into registers
        for (int r = 0; r < 32; ++r) {
            int g = gi[r];
            if ((g >> 3) == w) {
                float wv = swgt[r];
#pragma unroll
                for (int mi = 0; mi < 8; ++mi) {
                    if (g == w * 8 + mi) {
#pragma unroll
                        for (int i = 0; i < 8; ++i)
                            acc[mi][i] += wv * tile[(lane + 32 * i) * 33 + r];
                    }
                }
            }
        }
    }

    // epilogue: one global reduce per (m, d)
#pragma unroll
    for (int mi = 0; mi < 8; ++mi)
#pragma unroll
        for (int i = 0; i < 8; ++i)
            atomicAdd(&g_qupd[(w * 8 + mi) * 256 + lane + 32 * i], acc[mi][i]);
}

// ---------------- K7: updated_memory = normalize(qupd + keys) -----------------
__global__ __launch_bounds__(256) void k7_um(const float* __restrict__ keys,
                                             float* __restrict__ out_um) {
    __shared__ float wr[8];
    const int m = blockIdx.x, d = threadIdx.x;
    const int lane = d & 31, w = d >> 5;
    float val = g_qupd[m * 256 + d] + keys[m * 256 + d];
    float ss = val * val;
#pragma unroll
    for (int off = 16; off > 0; off >>= 1) ss += __shfl_xor_sync(0xffffffffu, ss, off);
    if (lane == 0) wr[w] = ss;
    __syncthreads();
    float tot = 0.0f;
#pragma unroll
    for (int i = 0; i < 8; ++i) tot += wr[i];
    float n = sqrtf(tot);
    float denom = fmaxf(n, 1e-12f);
    out_um[m * 256 + d] = val / denom;
}

// ---------------- launch -------------------------------------------------------
extern "C" void kernel_launch(void* const* d_in, const int* in_sizes, int n_in,
                              void* d_out, int out_size) {
    const float* query = (const float*)d_in[0];   // (256, 1024, 64)
    const float* keys  = (const float*)d_in[1];   // (64, 256)
    float* out = (float*)d_out;

    k0_init<<<64, 256>>>(keys);
    k1_score<<<256, 256>>>(query, out + OFF_SM, out + OFF_UQ, out + OFF_SP);
    k2_combine<<<64, 256>>>();
    k3_sq<<<1024, 256>>>(out + OFF_SM, out + OFF_SQ);
    k4_fused<<<512, 256>>>(query, keys, out + OFF_GL);
    k7_um<<<64, 256>>>(keys, out + OFF_UM);
}

// round 14
// speedup vs baseline: 2.6163x; 1.0003x over previous
#include <cuda_runtime.h>
#include <math.h>
#include <cstdint>

#define D 256
#define T_ 1024
#define NN 64
#define ROWS 65536   // T_*NN
#define M 64

// output layout (concatenated, fp32)
#define OFF_UQ 0UL                  // (512,1024,64) = 33554432
#define OFF_UM 33554432UL           // (64,256)      = 16384
#define OFF_SQ 33570816UL           // (65536,64)    = 4194304
#define OFF_SM 37765120UL           // (65536,64)    = 4194304
#define OFF_SP 41959424UL           // (65536,)      = 65536
#define OFF_GL 42024960UL           // (65536,256)   = 16777216

typedef unsigned long long ull;

// ---------------- scratch (static device globals; no allocations) ------------
__device__ float g_keysT[D * M];        // keys transposed [d][m]
__device__ float g_knorm[M];            // ||k_m||^2
__device__ float g_ksum[M];             // sum_d k_m[d]
__device__ float g_bmax[256 * M];       // per-block column max partials
__device__ float g_bsum[256 * M];       // per-block column sum partials (vs bmax)
__device__ float g_cmax[M];
__device__ float g_csum[M];
__device__ float g_sval[ROWS];          // row max = score at top1
__device__ float g_se[ROWS];            // row sum of exp(s - rowmax)
__device__ int   g_top1[ROWS];
__device__ int   g_top2i[ROWS];
__device__ float g_qupd[M * D];

// ---------------- scalar helpers ---------------------------------------------
__device__ __forceinline__ ull pack2(float lo, float hi) {
    ull r; asm("mov.b64 %0, {%1, %2};" : "=l"(r) : "f"(lo), "f"(hi)); return r;
}
__device__ __forceinline__ void unpack2(ull v, float& lo, float& hi) {
    asm("mov.b64 {%0, %1}, %2;" : "=f"(lo), "=f"(hi) : "l"(v));
}
__device__ __forceinline__ ull fma2(ull a, ull b, ull c) {
    ull d; asm("fma.rn.f32x2 %0, %1, %2, %3;" : "=l"(d) : "l"(a), "l"(b), "l"(c));
    return d;
}

// ---------------- K0a: keys transpose + zero qupd ------------------------------
__global__ __launch_bounds__(256) void k0a_init(const float* __restrict__ keys) {
    const int b = blockIdx.x;          // memory slot m
    const int t = threadIdx.x;         // d
    g_keysT[t * M + b] = keys[b * 256 + t];
    g_qupd[b * 256 + t] = 0.0f;
}

// ---------------- K0b: key norms -----------------------------------------------
__global__ __launch_bounds__(256) void k0b_norm(const float* __restrict__ keys) {
    __shared__ float rn[8];
    const int b = blockIdx.x, t = threadIdx.x;
    const int lane = t & 31, w = t >> 5;
    float kv = keys[b * 256 + t];
    float n2 = kv * kv;
#pragma unroll
    for (int off = 16; off > 0; off >>= 1) n2 += __shfl_xor_sync(0xffffffffu, n2, off);
    if (lane == 0) rn[w] = n2;
    __syncthreads();
    if (t == 0) {
        float tn = 0.0f;
#pragma unroll
        for (int i = 0; i < 8; ++i) tn += rn[i];
        g_knorm[b] = tn;
    }
}

// ---------------- K0c: key sums -------------------------------------------------
__global__ __launch_bounds__(256) void k0c_sum(const float* __restrict__ keys) {
    __shared__ float rs[8];
    const int b = blockIdx.x, t = threadIdx.x;
    const int lane = t & 31, w = t >> 5;
    float kv = keys[b * 256 + t];
#pragma unroll
    for (int off = 16; off > 0; off >>= 1) kv += __shfl_xor_sync(0xffffffffu, kv, off);
    if (lane == 0) rs[w] = kv;
    __syncthreads();
    if (t == 0) {
        float ts = 0.0f;
#pragma unroll
        for (int i = 0; i < 8; ++i) ts += rs[i];
        g_ksum[b] = ts;
    }
}

// ---------------- K1: score GEMM + softmaxes + top2 + spreading + concat GEMM -
__global__ __launch_bounds__(256, 2) void k1_score(const float* __restrict__ q,
                                                   float* __restrict__ out_sm,
                                                   float* __restrict__ out_uq,
                                                   float* __restrict__ out_sp) {
    __shared__ float sK[D * M];        // 64 KB keysT [d][m]
    __shared__ float wred[8 * 64];
    __shared__ float bmaxs[64];
    __shared__ float sKn[64], sKs[64];
    const int tid = threadIdx.x;
    const int row = blockIdx.x * 256 + tid;
    const int lane = tid & 31, wid = tid >> 5;

    {   // stage keysT to SMEM (coalesced)
        const float4* src = (const float4*)g_keysT;
        float4* dst = (float4*)sK;
#pragma unroll
        for (int i = 0; i < 16; ++i) dst[i * 256 + tid] = src[i * 256 + tid];
        if (tid < 64) { sKn[tid] = g_knorm[tid]; sKs[tid] = g_ksum[tid]; }
    }
    __syncthreads();

    ull acc[32];
#pragma unroll
    for (int j = 0; j < 32; ++j) acc[j] = 0ull;
    float nq2 = 0.0f, sumq = 0.0f;

    const ulonglong2* ks2 = (const ulonglong2*)sK;

    for (int d0 = 0; d0 < D; d0 += 8) {
        float qv[8];
#pragma unroll
        for (int u = 0; u < 8; ++u) qv[u] = __ldg(&q[(d0 + u) * ROWS + row]);
#pragma unroll
        for (int u = 0; u < 8; ++u) {      // free updated_query[:256] copy (streaming)
            __stcs(&out_uq[(size_t)(d0 + u) * ROWS + row], qv[u]);
            nq2 = fmaf(qv[u], qv[u], nq2);
            sumq += qv[u];
        }
#pragma unroll
        for (int u = 0; u < 8; ++u) {
            ull q2 = pack2(qv[u], qv[u]);
#pragma unroll
            for (int jj = 0; jj < 16; ++jj) {
                ulonglong2 kk = ks2[(d0 + u) * 16 + jj];
                acc[2 * jj]     = fma2(q2, kk.x, acc[2 * jj]);
                acc[2 * jj + 1] = fma2(q2, kk.y, acc[2 * jj + 1]);
            }
        }
    }

    float s[64];
#pragma unroll
    for (int j = 0; j < 32; ++j) unpack2(acc[j], s[2 * j], s[2 * j + 1]);

    // top-2 (strict > keeps lowest index on ties, matching lax.top_k)
    float v1 = -1e30f, v2 = -1e30f; int i1 = 0, i2 = 0;
#pragma unroll
    for (int m = 0; m < 64; ++m) {
        float v = s[m];
        if (v > v1) { v2 = v1; i2 = i1; v1 = v; i1 = m; }
        else if (v > v2) { v2 = v; i2 = m; }
    }
    g_top1[row] = i1;
    g_top2i[row] = i2;
    g_sval[row] = v1;

    // spreading_loss via algebraic identity:
    // ||q - k + e||^2 = ||q||^2 - 2 s + ||k||^2 + 2e(sum q - sum k) + 256 e^2
    {
        const float e = 1e-6f;
        float dp2 = nq2 - 2.0f * v1 + sKn[i1] + 2.0f * e * (sumq - sKs[i1]) + 256.0f * e * e;
        float dn2 = nq2 - 2.0f * v2 + sKn[i2] + 2.0f * e * (sumq - sKs[i2]) + 256.0f * e * e;
        out_sp[row] = fmaxf(sqrtf(fmaxf(dp2, 0.0f)) - sqrtf(fmaxf(dn2, 0.0f)) + 1.0f, 0.0f);
    }

    // block column-max partials
#pragma unroll
    for (int m = 0; m < 64; ++m) {
        float v = s[m];
        v = fmaxf(v, __shfl_xor_sync(0xffffffffu, v, 16));
        v = fmaxf(v, __shfl_xor_sync(0xffffffffu, v, 8));
        v = fmaxf(v, __shfl_xor_sync(0xffffffffu, v, 4));
        v = fmaxf(v, __shfl_xor_sync(0xffffffffu, v, 2));
        v = fmaxf(v, __shfl_xor_sync(0xffffffffu, v, 1));
        if (lane == 0) wred[wid * 64 + m] = v;
    }
    __syncthreads();
    if (tid < 64) {
        float mx = wred[tid];
#pragma unroll
        for (int w = 1; w < 8; ++w) mx = fmaxf(mx, wred[w * 64 + tid]);
        bmaxs[tid] = mx;
        g_bmax[blockIdx.x * 64 + tid] = mx;
    }
    __syncthreads();

    // block column-sum partials w.r.t. block max (online softmax merge later)
#pragma unroll
    for (int m = 0; m < 64; ++m) {
        float c = __expf(s[m] - bmaxs[m]);
        c += __shfl_xor_sync(0xffffffffu, c, 16);
        c += __shfl_xor_sync(0xffffffffu, c, 8);
        c += __shfl_xor_sync(0xffffffffu, c, 4);
        c += __shfl_xor_sync(0xffffffffu, c, 2);
        c += __shfl_xor_sync(0xffffffffu, c, 1);
        if (lane == 0) wred[wid * 64 + m] = c;
    }
    __syncthreads();
    if (tid < 64) {
        float sm = 0.0f;
#pragma unroll
        for (int w = 0; w < 8; ++w) sm += wred[w * 64 + tid];
        g_bsum[blockIdx.x * 64 + tid] = sm;
    }

    // row softmax -> probabilities (== score_memory row)
    float se = 0.0f;
#pragma unroll
    for (int m = 0; m < 64; ++m) { s[m] = __expf(s[m] - v1); se += s[m]; }
    g_se[row] = se;
    float inv = 1.0f / se;
#pragma unroll
    for (int m = 0; m < 64; ++m) s[m] *= inv;
#pragma unroll
    for (int j = 0; j < 16; ++j) {
        float4 t = make_float4(s[4 * j], s[4 * j + 1], s[4 * j + 2], s[4 * j + 3]);
        ((float4*)(out_sm + (size_t)row * 64))[j] = t;   // sm IS re-read -> keep in L2
    }

    // ---- fused concat_memory GEMM: updated_query[256:] = P @ keys ----
    ull p2[32];
#pragma unroll
    for (int j = 0; j < 32; ++j) p2[j] = pack2(s[2 * j], s[2 * j + 1]);

#pragma unroll 4
    for (int d = 0; d < D; ++d) {
        ull a0 = 0ull, a1 = 0ull;
#pragma unroll
        for (int jj = 0; jj < 16; ++jj) {
            ulonglong2 kk = ks2[d * 16 + jj];
            a0 = fma2(p2[2 * jj],     kk.x, a0);
            a1 = fma2(p2[2 * jj + 1], kk.y, a1);
        }
        float l0, h0, l1, h1;
        unpack2(a0, l0, h0); unpack2(a1, l1, h1);
        __stcs(&out_uq[(size_t)(256 + d) * ROWS + row], (l0 + h0) + (l1 + h1));
    }
}

// ---------------- K2: combine per-block partials ------------------------------
__global__ __launch_bounds__(256) void k2_combine() {   // grid 64 (one per m)
    __shared__ float red[256];
    const int m = blockIdx.x, t = threadIdx.x;
    float bm = g_bmax[t * 64 + m];
    red[t] = bm;
    __syncthreads();
#pragma unroll
    for (int s = 128; s > 0; s >>= 1) {
        if (t < s) red[t] = fmaxf(red[t], red[t + s]);
        __syncthreads();
    }
    float cmax = red[0];
    __syncthreads();
    red[t] = g_bsum[t * 64 + m] * __expf(bm - cmax);
    __syncthreads();
#pragma unroll
    for (int s = 128; s > 0; s >>= 1) {
        if (t < s) red[t] += red[t + s];
        __syncthreads();
    }
    if (t == 0) { g_cmax[m] = cmax; g_csum[m] = red[0]; }
}

// ---------------- K3: score_query reconstructed from score_memory -------------
// sq[r][m] = sm[r][m] * se_r * exp(v1_r - cmax_m) / csum_m
__global__ __launch_bounds__(256) void k3_sq(const float* __restrict__ sm_in,
                                             float* __restrict__ out_sq) {
    __shared__ float cm[64], iv[64];
    const int tid = threadIdx.x;
    if (tid < 64) { cm[tid] = g_cmax[tid]; iv[tid] = 1.0f / g_csum[tid]; }
    __syncthreads();
    const float4* src = (const float4*)sm_in;
    float4* dst = (float4*)out_sq;
    const int base = blockIdx.x * 256 + tid;   // grid 1024 -> 262144 threads
#pragma unroll
    for (int r = 0; r < 4; ++r) {
        int i4 = base + r * 262144;
        int row = i4 >> 4;
        float v1 = __ldg(&g_sval[row]);
        float se = __ldg(&g_se[row]);
        int m0 = (i4 << 2) & 63;
        float4 v = src[i4];
        float4 o;
        o.x = v.x * se * __expf(v1 - cm[m0])     * iv[m0];
        o.y = v.y * se * __expf(v1 - cm[m0 + 1]) * iv[m0 + 1];
        o.z = v.z * se * __expf(v1 - cm[m0 + 2]) * iv[m0 + 2];
        o.w = v.w * se * __expf(v1 - cm[m0 + 3]) * iv[m0 + 3];
        __stcs(&dst[i4], o);
    }
}

// ---------------- K4f: gathering_loss + query_update scatter (fused) ----------
// grid 512 x 128 rows; warp w owns memories [8w, 8w+8); lane covers d = lane+32i.
__global__ __launch_bounds__(256, 2) void k4_fused(const float* __restrict__ q,
                                                   const float* __restrict__ keys,
                                                   float* __restrict__ out_gl) {
    __shared__ float tile[256 * 33];   // [d][r]
    __shared__ int   gi[32];
    __shared__ float swgt[32];
    __shared__ float scm[64];

    const int tid = threadIdx.x;
    const int lane = tid & 31, w = tid >> 5;
    const int rowbase = blockIdx.x * 128;

    if (tid < 64) scm[tid] = g_cmax[tid];

    float acc[8][8];   // [mi][i]
#pragma unroll
    for (int mi = 0; mi < 8; ++mi)
#pragma unroll
        for (int i = 0; i < 8; ++i) acc[mi][i] = 0.0f;

    for (int c = 0; c < 4; ++c) {
        const int row0 = rowbase + c * 32;
        __syncthreads();   // previous chunk's readers done; scm ready (c==0)
        if (tid < 32) {
            int g = g_top1[row0 + tid];
            gi[tid] = g;
            swgt[tid] = __expf(g_sval[row0 + tid] - scm[g]);
        }
        // phase A: coalesced load of 32x256 q chunk into [d][r] tile
        {
            const int r = lane, dg = w;
#pragma unroll 8
            for (int it = 0; it < 32; ++it) {
                int d = it * 8 + dg;
                tile[d * 33 + r] = q[(size_t)d * ROWS + row0 + r];
            }
        }
        __syncthreads();

        // phase B: gathering_loss only (d = tid across threads, coalesced)
        const int d = tid;
#pragma unroll 4
        for (int it = 0; it < 32; ++it) {
            int g = gi[it];
            float qv = tile[d * 33 + it];
            float kp = __ldg(&keys[g * 256 + d]);
            float df = qv - kp;
            __stcs(&out_gl[(size_t)(row0 + it) * 256 + d], df * df);
        }

        // phase C: warp-owned scatter-reduce into registers
        for (int r = 0; r < 32; ++r) {
            int g = gi[r];
            if ((g >> 3) == w) {
                float wv = swgt[r];
#pragma unroll
                for (int mi = 0; mi < 8; ++mi) {
                    if (g == w * 8 + mi) {
#pragma unroll
                        for (int i = 0; i < 8; ++i)
                            acc[mi][i] += wv * tile[(lane + 32 * i) * 33 + r];
                    }
                }
            }
        }
    }

    // epilogue: one global reduce per (m, d)
#pragma unroll
    for (int mi = 0; mi < 8; ++mi)
#pragma unroll
        for (int i = 0; i < 8; ++i)
            atomicAdd(&g_qupd[(w * 8 + mi) * 256 + lane + 32 * i], acc[mi][i]);
}

// ---------------- K7: updated_memory = normalize(qupd + keys) -----------------
__global__ __launch_bounds__(256) void k7_um(const float* __restrict__ keys,
                                             float* __restrict__ out_um) {
    __shared__ float wr[8];
    const int m = blockIdx.x, d = threadIdx.x;
    const int lane = d & 31, w = d >> 5;
    float val = g_qupd[m * 256 + d] + keys[m * 256 + d];
    float ss = val * val;
#pragma unroll
    for (int off = 16; off > 0; off >>= 1) ss += __shfl_xor_sync(0xffffffffu, ss, off);
    if (lane == 0) wr[w] = ss;
    __syncthreads();
    float tot = 0.0f;
#pragma unroll
    for (int i = 0; i < 8; ++i) tot += wr[i];
    float n = sqrtf(tot);
    float denom = fmaxf(n, 1e-12f);
    out_um[m * 256 + d] = val / denom;
}

// ---------------- launch -------------------------------------------------------
extern "C" void kernel_launch(void* const* d_in, const int* in_sizes, int n_in,
                              void* d_out, int out_size) {
    const float* query = (const float*)d_in[0];   // (256, 1024, 64)
    const float* keys  = (const float*)d_in[1];   // (64, 256)
    float* out = (float*)d_out;

    k0a_init<<<64, 256>>>(keys);
    k0b_norm<<<64, 256>>>(keys);
    k0c_sum<<<64, 256>>>(keys);
    k1_score<<<256, 256>>>(query, out + OFF_SM, out + OFF_UQ, out + OFF_SP);
    k2_combine<<<64, 256>>>();
    k3_sq<<<1024, 256>>>(out + OFF_SM, out + OFF_SQ);
    k4_fused<<<512, 256>>>(query, keys, out + OFF_GL);
    k7_um<<<64, 256>>>(keys, out + OFF_UM);
}